// round 14
// baseline (speedup 1.0000x reference)
#include <cuda_runtime.h>
#include <cuda_bf16.h>
#include <cstdint>
#include <math.h>

#define NN 64
#define BB 32
#define EE 4032
#define FF 256
#define BIG_M  (BB*EE)       // 129024
#define NODE_M (BB*NN)       // 2048
#define BIG_CH (BIG_M/128)   // 1008
#define NODE_CH (NODE_M/32)  // 64

// ---------------- scratch ----------------
__device__ float g_nodeA[NODE_M*FF];
__device__ float g_nodeB[NODE_M*FF];
__device__ float g_nodeC[NODE_M*FF];
__device__ float g_nodeD[NODE_M*FF];
__device__ float g_PQ[NODE_M*2*FF];
__device__ float g_SR[NODE_M*2*FF];
__device__ float g_inc[NODE_M*FF];
__device__ float g_bigA[(size_t)BIG_M*FF];
__device__ float g_bigB[(size_t)BIG_M*FF];
__device__ float g_psum[BIG_CH*FF];
__device__ float g_psq[BIG_CH*FF];
__device__ float g_scale[4*FF];
__device__ float g_shift[4*FF];
__device__ float g_dbias[FF];
__device__ float g_biasPQ[2*FF];
__device__ float g_fcw2[2*FF];
__device__ float g_fcb2[2];
__device__ __nv_bfloat16 g_WL1hi[FF*FF], g_WL1lo[FF*FF];
__device__ __nv_bfloat16 g_WL2hi[FF*FF], g_WL2lo[FF*FF];
__device__ __nv_bfloat16 g_WL3hi[FF*FF], g_WL3lo[FF*FF];
__device__ __nv_bfloat16 g_WL4hi[FF*FF], g_WL4lo[FF*FF];
__device__ __nv_bfloat16 g_WPQhi[2*FF*FF], g_WPQlo[2*FF*FF];
__device__ __nv_bfloat16 g_WSRhi[2*FF*FF], g_WSRlo[2*FF*FF];
__device__ __nv_bfloat16 g_W2hi[FF*FF],  g_W2lo[FF*FF];
__device__ __nv_bfloat16 g_W4hi[FF*FF],  g_W4lo[FF*FF];
__device__ __nv_bfloat16 g_WSKhi[FF*FF], g_WSKlo[FF*FF];

__device__ __forceinline__ float eluf(float x){ return x > 0.f ? x : expm1f(x); }

__device__ __forceinline__ uint32_t smem_u32(const void* p){
    uint32_t a;
    asm("{ .reg .u64 t; cvta.to.shared.u64 t, %1; cvt.u32.u64 %0, t; }" : "=r"(a) : "l"(p));
    return a;
}

#define LDSM4(r0,r1,r2,r3, addr) \
    asm volatile("ldmatrix.sync.aligned.m8n8.x4.shared.b16 {%0,%1,%2,%3}, [%4];" \
        : "=r"(r0),"=r"(r1),"=r"(r2),"=r"(r3) : "r"(addr))

#define MMA4(d, a0,a1,a2,a3, b0,b1) \
    asm volatile("mma.sync.aligned.m16n8k16.row.col.f32.bf16.bf16.f32 " \
        "{%0,%1,%2,%3},{%4,%5,%6,%7},{%8,%9},{%0,%1,%2,%3};" \
        : "+f"((d)[0]),"+f"((d)[1]),"+f"((d)[2]),"+f"((d)[3]) \
        : "r"(a0),"r"(a1),"r"(a2),"r"(a3),"r"(b0),"r"(b1))

__device__ __forceinline__ uint32_t pk2(float a, float b){
    __nv_bfloat16 ha = __float2bfloat16(a), hb = __float2bfloat16(b);
    return (uint32_t)(*(uint16_t*)&ha) | ((uint32_t)(*(uint16_t*)&hb) << 16);
}
__device__ __forceinline__ void split2(float x, float y, uint32_t& hi, uint32_t& lo){
    __nv_bfloat16 hx = __float2bfloat16(x), hy = __float2bfloat16(y);
    hi = (uint32_t)(*(uint16_t*)&hx) | ((uint32_t)(*(uint16_t*)&hy) << 16);
    lo = pk2(x - __bfloat162float(hx), y - __bfloat162float(hy));
}

// ============ big HMMA GEMM v2: 128 rows x 128 cols per CTA, 256 thr, 2 CTAs/SM ============
// AMODE 0: A direct fp32; AMODE 2: A[r][k] = elu(A[po]+PB[qo]) (pitch-512 gathers)
// SRE: epilogue adds Sg[po]+Rg[qo]+db
#define H2_PO    0
#define H2_QO    512
#define H2_AHI   1024
#define H2_ALO   11264
#define H2_BHI   21504
#define H2_BLO   31744
#define H2_STAGE 1024
#define SMEM_H2  41984

template<int AMODE, bool DOELU, bool STATS, bool SRE>
__global__ __launch_bounds__(256, 2) void hgemm2(
    const float* __restrict__ A, const float* __restrict__ PB,
    const __nv_bfloat16* __restrict__ Whi, const __nv_bfloat16* __restrict__ Wlo,
    const float* __restrict__ bias,
    const float* __restrict__ Sg, const float* __restrict__ Rg, const float* __restrict__ db,
    float* __restrict__ C, float* __restrict__ pSum, float* __restrict__ pSq)
{
    extern __shared__ __align__(1024) char smem[];
    const uint32_t sb = smem_u32(smem);
    const int tid = threadIdx.x, wid = tid >> 5, l = tid & 31;
    const int rowbase = blockIdx.x * 128;
    const int cb = blockIdx.y * 128;
    int* po = (int*)(smem + H2_PO);
    int* qo = (int*)(smem + H2_QO);

    if (AMODE == 2 || SRE) {
        if (tid < 128) {
            int gr = rowbase + tid;
            int b = gr / EE; int e = gr - b*EE;
            int snd = e / 63; int jp = e - snd*63; int rcv = jp + (jp >= snd ? 1 : 0);
            po[tid] = (b*NN + snd)*512;
            qo[tid] = (b*NN + rcv)*512;
        }
        __syncthreads();
    }

    const int m0  = (wid & 3) * 32;     // 4 m-groups of 32 rows
    const int n0w = (wid >> 2) * 64;    // 2 n-groups of 64 cols

    float acc[2][8][4];
    #pragma unroll
    for (int i=0;i<2;i++)
        #pragma unroll
        for (int j=0;j<8;j++)
            #pragma unroll
            for (int q=0;q<4;q++) acc[i][j][q]=0.f;

    const uint32_t aHiBase = sb + H2_AHI + (uint32_t)((m0 + (l & 15)) * 80 + ((l >> 4) << 4));
    const int bro = (l & 7) + ((l >> 4) << 3);
    const uint32_t bHiBase = sb + H2_BHI + (uint32_t)((n0w + bro) * 80 + ((l & 8) ? 16 : 0));

    const int prow = tid >> 1, pko = (tid & 1) * 16;   // A: 128r x 32k, 16 el/thread
    const int bnr  = tid >> 1, bko = (tid & 1) * 16;   // B: 128n x 32k, 16 el/thread

    uint4 bvh0, bvh1, bvl0, bvl1;
    auto loadB = [&](int ks){
        const size_t go = (size_t)(cb + bnr)*FF + ks*32 + bko;
        bvh0 = *(const uint4*)(Whi + go); bvh1 = *(const uint4*)(Whi + go + 8);
        bvl0 = *(const uint4*)(Wlo + go); bvl1 = *(const uint4*)(Wlo + go + 8);
    };

    loadB(0);
    for (int ks = 0; ks < 8; ks++) {
        const int k0 = ks * 32;
        // ---- A: load + convert + store (not prefetched; 2nd CTA hides latency) ----
        {
            float e16[16];
            if (AMODE == 2) {
                const float* pa = A  + po[prow] + k0 + pko;
                const float* pb = PB + qo[prow] + k0 + pko;
                #pragma unroll
                for (int q = 0; q < 4; q++) {
                    float4 a4 = *(const float4*)(pa + q*4);
                    float4 b4 = *(const float4*)(pb + q*4);
                    e16[q*4+0]=eluf(a4.x+b4.x); e16[q*4+1]=eluf(a4.y+b4.y);
                    e16[q*4+2]=eluf(a4.z+b4.z); e16[q*4+3]=eluf(a4.w+b4.w);
                }
            } else {
                const float* pa = A + (size_t)(rowbase+prow)*FF + k0 + pko;
                #pragma unroll
                for (int q = 0; q < 4; q++) {
                    float4 a4 = *(const float4*)(pa + q*4);
                    e16[q*4+0]=a4.x; e16[q*4+1]=a4.y; e16[q*4+2]=a4.z; e16[q*4+3]=a4.w;
                }
            }
            uint32_t hi[8], lo[8];
            #pragma unroll
            for (int q = 0; q < 8; q++) split2(e16[2*q], e16[2*q+1], hi[q], lo[q]);
            char* ah = smem + H2_AHI + prow*80 + pko*2;
            char* al = smem + H2_ALO + prow*80 + pko*2;
            *(uint4*)ah      = make_uint4(hi[0],hi[1],hi[2],hi[3]);
            *(uint4*)(ah+16) = make_uint4(hi[4],hi[5],hi[6],hi[7]);
            *(uint4*)al      = make_uint4(lo[0],lo[1],lo[2],lo[3]);
            *(uint4*)(al+16) = make_uint4(lo[4],lo[5],lo[6],lo[7]);
        }
        // ---- B store from prefetch regs ----
        {
            char* bh = smem + H2_BHI + bnr*80 + bko*2;
            char* bl = smem + H2_BLO + bnr*80 + bko*2;
            *(uint4*)bh = bvh0; *(uint4*)(bh+16) = bvh1;
            *(uint4*)bl = bvl0; *(uint4*)(bl+16) = bvl1;
        }
        __syncthreads();
        if (ks < 7) loadB(ks + 1);    // B prefetch behind MMAs

        #pragma unroll
        for (int ksub = 0; ksub < 2; ksub++) {
            uint32_t ah[2][4], alr[2][4];
            #pragma unroll
            for (int mt = 0; mt < 2; mt++) {
                uint32_t ad = aHiBase + (uint32_t)(mt*16*80 + ksub*32);
                LDSM4(ah[mt][0],ah[mt][1],ah[mt][2],ah[mt][3], ad);
                LDSM4(alr[mt][0],alr[mt][1],alr[mt][2],alr[mt][3], ad + (H2_ALO-H2_AHI));
            }
            uint32_t bhc[4], bloc[4], bhn[4], blon[4];
            {
                uint32_t bd = bHiBase + (uint32_t)(ksub*32);
                LDSM4(bhc[0],bhc[1],bhc[2],bhc[3], bd);
                LDSM4(bloc[0],bloc[1],bloc[2],bloc[3], bd + (H2_BLO-H2_BHI));
            }
            #pragma unroll
            for (int nt2 = 0; nt2 < 4; nt2++) {
                if (nt2 < 3) {
                    uint32_t bd = bHiBase + (uint32_t)((nt2+1)*16*80 + ksub*32);
                    LDSM4(bhn[0],bhn[1],bhn[2],bhn[3], bd);
                    LDSM4(blon[0],blon[1],blon[2],blon[3], bd + (H2_BLO-H2_BHI));
                }
                #pragma unroll
                for (int mt = 0; mt < 2; mt++) {
                    #pragma unroll
                    for (int t = 0; t < 2; t++) {
                        float* d = acc[mt][nt2*2+t];
                        MMA4(d, ah[mt][0],ah[mt][1],ah[mt][2],ah[mt][3],  bhc[t*2], bhc[t*2+1]);
                        MMA4(d, ah[mt][0],ah[mt][1],ah[mt][2],ah[mt][3],  bloc[t*2], bloc[t*2+1]);
                        MMA4(d, alr[mt][0],alr[mt][1],alr[mt][2],alr[mt][3], bhc[t*2], bhc[t*2+1]);
                    }
                }
                #pragma unroll
                for (int q = 0; q < 4; q++) { bhc[q] = bhn[q]; bloc[q] = blon[q]; }
            }
        }
        __syncthreads();
    }

    // ---- epilogue: two 64-col halves via SMEM stage [128][65] ----
    float* stage = (float*)(smem + H2_STAGE);
    float sS[4], sQ2[4];
    #pragma unroll
    for (int g = 0; g < 4; g++){ sS[g]=0.f; sQ2[g]=0.f; }

    for (int h = 0; h < 2; h++) {
        if ((wid >> 2) == h) {
            #pragma unroll
            for (int mt = 0; mt < 2; mt++) {
                #pragma unroll
                for (int nt = 0; nt < 8; nt++) {
                    int r = m0 + mt*16 + (l >> 2);
                    int c = nt*8 + (l & 3)*2;
                    stage[r*65 + c]       = acc[mt][nt][0];
                    stage[r*65 + c + 1]   = acc[mt][nt][1];
                    stage[(r+8)*65 + c]   = acc[mt][nt][2];
                    stage[(r+8)*65 + c+1] = acc[mt][nt][3];
                }
            }
        }
        __syncthreads();
        #pragma unroll
        for (int rr = 0; rr < 16; rr++) {
            int r = wid*16 + rr;
            float* cp = C + (size_t)(rowbase + r)*FF + cb + h*64;
            const float* srP = nullptr; const float* srQ = nullptr;
            if (SRE) { srP = Sg + po[r] + cb + h*64; srQ = Rg + qo[r] + cb + h*64; }
            #pragma unroll
            for (int g = 0; g < 2; g++) {
                int c = g*32 + l;
                float f = stage[r*65 + c];
                if (bias) f += bias[cb + h*64 + c];
                if (SRE)  f += srP[c] + srQ[c] + db[cb + h*64 + c];
                if (DOELU) f = eluf(f);
                cp[c] = f;
                if (STATS) { int s = h*2+g; sS[s] += f; sQ2[s] = fmaf(f, f, sQ2[s]); }
            }
        }
        __syncthreads();
    }

    if (STATS) {
        float* xs = stage;            // [8][128]
        float* xq = stage + 1024;     // [8][128]
        #pragma unroll
        for (int s = 0; s < 4; s++) {
            int c = (s>>1)*64 + (s&1)*32 + l;
            xs[wid*128 + c] = sS[s];
            xq[wid*128 + c] = sQ2[s];
        }
        __syncthreads();
        if (tid < 128) {
            float s=0.f, q=0.f;
            #pragma unroll
            for (int w = 0; w < 8; w++){ s += xs[w*128 + tid]; q += xq[w*128 + tid]; }
            pSum[(size_t)blockIdx.x*FF + cb + tid] = s;
            pSq [(size_t)blockIdx.x*FF + cb + tid] = q;
        }
    }
}

// ============ node HMMA GEMM (R8 proven, unchanged) ============
#define N_AHI 0
#define N_ALO 2560
#define N_BHI 5120
#define N_BLO 15360
#define N_SMEM 25600
template<int AMODE, bool DOELU, bool STATS>
__global__ __launch_bounds__(256) void ngemm(
    const float* __restrict__ A,
    const __nv_bfloat16* __restrict__ Whi, const __nv_bfloat16* __restrict__ Wlo,
    const float* __restrict__ bias,
    const float* __restrict__ aSc, const float* __restrict__ aSh,
    int ldc,
    float* __restrict__ C, float* __restrict__ pSum, float* __restrict__ pSq)
{
    __shared__ __align__(1024) char smem[N_SMEM];
    const uint32_t sb = smem_u32(smem);
    const int tid = threadIdx.x, wid = tid >> 5, l = tid & 31;
    const int rowbase = blockIdx.x * 32;
    const int cb = blockIdx.y * 128;

    const int m0  = (wid & 1) * 16;
    const int n0w = (wid >> 1) * 32;

    float acc[4][4];
    #pragma unroll
    for (int j=0;j<4;j++)
        #pragma unroll
        for (int q=0;q<4;q++) acc[j][q]=0.f;

    const uint32_t aHiBase = sb + N_AHI + (uint32_t)((m0 + (l & 15)) * 80 + ((l >> 4) << 4));
    const int bro = (l & 7) + ((l >> 4) << 3);
    const uint32_t bHiBase = sb + N_BHI + (uint32_t)((n0w + bro) * 80 + ((l & 8) ? 16 : 0));

    const int prow = tid >> 3, pko = (tid & 7) * 4;
    const int bnr  = tid >> 1, bko = (tid & 1) * 16;

    float4 fa;
    uint4 bvh0, bvh1, bvl0, bvl1;
    auto loadStage = [&](int ks){
        const int k0 = ks * 32;
        fa = *(const float4*)(A + (size_t)(rowbase+prow)*FF + k0 + pko);
        if (AMODE == 1) {
            const float4 sc = *(const float4*)(aSc + k0 + pko);
            const float4 sh = *(const float4*)(aSh + k0 + pko);
            fa.x = fmaf(sc.x, fa.x, sh.x); fa.y = fmaf(sc.y, fa.y, sh.y);
            fa.z = fmaf(sc.z, fa.z, sh.z); fa.w = fmaf(sc.w, fa.w, sh.w);
        }
        const size_t go = (size_t)(cb + bnr)*FF + k0 + bko;
        bvh0 = *(const uint4*)(Whi + go); bvh1 = *(const uint4*)(Whi + go + 8);
        bvl0 = *(const uint4*)(Wlo + go); bvl1 = *(const uint4*)(Wlo + go + 8);
    };

    loadStage(0);
    for (int ks = 0; ks < 8; ks++) {
        {
            uint32_t h0, l0, h1, l1;
            split2(fa.x, fa.y, h0, l0);
            split2(fa.z, fa.w, h1, l1);
            char* ah = smem + N_AHI + prow*80 + pko*2;
            char* al = smem + N_ALO + prow*80 + pko*2;
            *(uint2*)ah = make_uint2(h0, h1);
            *(uint2*)al = make_uint2(l0, l1);
        }
        {
            char* bh = smem + N_BHI + bnr*80 + bko*2;
            char* bl = smem + N_BLO + bnr*80 + bko*2;
            *(uint4*)bh = bvh0; *(uint4*)(bh+16) = bvh1;
            *(uint4*)bl = bvl0; *(uint4*)(bl+16) = bvl1;
        }
        __syncthreads();
        if (ks < 7) loadStage(ks + 1);

        #pragma unroll
        for (int ksub = 0; ksub < 2; ksub++) {
            uint32_t ah[4], alr[4];
            uint32_t ad = aHiBase + (uint32_t)(ksub*32);
            LDSM4(ah[0],ah[1],ah[2],ah[3], ad);
            LDSM4(alr[0],alr[1],alr[2],alr[3], ad + (N_ALO-N_AHI));
            uint32_t bhc[4], bloc[4], bhn[4], blon[4];
            {
                uint32_t bd = bHiBase + (uint32_t)(ksub*32);
                LDSM4(bhc[0],bhc[1],bhc[2],bhc[3], bd);
                LDSM4(bloc[0],bloc[1],bloc[2],bloc[3], bd + (N_BLO-N_BHI));
            }
            #pragma unroll
            for (int nt2 = 0; nt2 < 2; nt2++) {
                if (nt2 < 1) {
                    uint32_t bd = bHiBase + (uint32_t)(16*80 + ksub*32);
                    LDSM4(bhn[0],bhn[1],bhn[2],bhn[3], bd);
                    LDSM4(blon[0],blon[1],blon[2],blon[3], bd + (N_BLO-N_BHI));
                }
                #pragma unroll
                for (int t = 0; t < 2; t++) {
                    float* d = acc[nt2*2+t];
                    MMA4(d, ah[0],ah[1],ah[2],ah[3],   bhc[t*2], bhc[t*2+1]);
                    MMA4(d, ah[0],ah[1],ah[2],ah[3],   bloc[t*2], bloc[t*2+1]);
                    MMA4(d, alr[0],alr[1],alr[2],alr[3], bhc[t*2], bhc[t*2+1]);
                }
                #pragma unroll
                for (int q = 0; q < 4; q++) { bhc[q] = bhn[q]; bloc[q] = blon[q]; }
            }
        }
        __syncthreads();
    }

    float* stage = (float*)smem;
    #pragma unroll
    for (int nt = 0; nt < 4; nt++) {
        int r = m0 + (l >> 2);
        int c = n0w + nt*8 + (l & 3)*2;
        stage[r*129 + c]       = acc[nt][0];
        stage[r*129 + c + 1]   = acc[nt][1];
        stage[(r+8)*129 + c]   = acc[nt][2];
        stage[(r+8)*129 + c+1] = acc[nt][3];
    }
    __syncthreads();

    float sS[4], sQ2[4];
    #pragma unroll
    for (int g = 0; g < 4; g++){ sS[g]=0.f; sQ2[g]=0.f; }
    #pragma unroll
    for (int rr = 0; rr < 4; rr++) {
        int r = wid*4 + rr;
        float* cp = C + (size_t)(rowbase + r)*ldc + cb;
        #pragma unroll
        for (int g = 0; g < 4; g++) {
            int c = g*32 + l;
            float f = stage[r*129 + c];
            if (bias) f += bias[cb + c];
            if (DOELU) f = eluf(f);
            cp[c] = f;
            if (STATS) { sS[g] += f; sQ2[g] = fmaf(f, f, sQ2[g]); }
        }
    }
    if (STATS) {
        __syncthreads();
        float* xs = (float*)(smem + 16512);
        float* xq = (float*)(smem + 20608);
        #pragma unroll
        for (int g = 0; g < 4; g++) {
            xs[wid*128 + g*32 + l] = sS[g];
            xq[wid*128 + g*32 + l] = sQ2[g];
        }
        __syncthreads();
        if (tid < 128) {
            float s=0.f, q=0.f;
            #pragma unroll
            for (int w = 0; w < 8; w++){ s += xs[w*128 + tid]; q += xq[w*128 + tid]; }
            pSum[(size_t)blockIdx.x*FF + cb + tid] = s;
            pSq [(size_t)blockIdx.x*FF + cb + tid] = q;
        }
    }
}

// ---------------- small kernels ----------------
__global__ void finalize_bn(const float* __restrict__ pSum, const float* __restrict__ pSq,
                            int nchunks, const float* __restrict__ g, const float* __restrict__ beta,
                            float invM, float* __restrict__ sc, float* __restrict__ sh)
{
    __shared__ float rs[256], rq[256];
    int lane = threadIdx.x & 31, part = threadIdx.x >> 5;
    int f = blockIdx.x*32 + lane;
    float s=0.f, q=0.f;
    for (int c=part; c<nchunks; c+=8){ s += pSum[(size_t)c*FF+f]; q += pSq[(size_t)c*FF+f]; }
    rs[threadIdx.x]=s; rq[threadIdx.x]=q;
    __syncthreads();
    if (part == 0){
        #pragma unroll
        for (int w=1; w<8; w++){ s += rs[w*32+lane]; q += rq[w*32+lane]; }
        float mean = s*invM;
        float var  = fmaf(-mean, mean, q*invM);
        float a = g[f]*rsqrtf(var + 1e-5f);
        sc[f]=a; sh[f] = fmaf(-mean, a, beta[f]);
    }
}

__global__ void edge2node_k(const float* __restrict__ h2, const float* __restrict__ sc,
                            const float* __restrict__ sh, float* __restrict__ inc)
{
    int bn = blockIdx.x; int b = bn >> 6; int n = bn & 63; int f = threadIdx.x;
    const float* base = h2 + (size_t)b*EE*FF + f;
    float s = 0.f;
    #pragma unroll
    for (int j=0;j<NN;j++){
        if (j==n) continue;
        int e = j*63 + (j < n ? n-1 : n);
        s += base[(size_t)e*FF];
    }
    inc[(size_t)bn*FF+f] = (sc[f]*s + 63.f*sh[f]) * (1.f/64.f);
}

struct TJob { const float* src; int srcOff; __nv_bfloat16* dhi; __nv_bfloat16* dlo; int dstOff; };
struct TJobs10 { TJob j[10]; };
__global__ void tsplit_all(TJobs10 P)
{
    __shared__ float t[32][33];
    TJob jb = P.j[blockIdx.z];
    int k0 = blockIdx.x*32, n0 = blockIdx.y*32;
    int tx = threadIdx.x, ty = threadIdx.y;
    t[ty][tx] = jb.src[(size_t)(jb.srcOff + k0+ty)*FF + n0+tx];
    __syncthreads();
    float v = t[tx][ty];
    __nv_bfloat16 h = __float2bfloat16(v);
    jb.dhi[(size_t)(jb.dstOff + n0+ty)*FF + k0+tx] = h;
    jb.dlo[(size_t)(jb.dstOff + n0+ty)*FF + k0+tx] = __float2bfloat16(v - __bfloat162float(h));
}

__global__ void tsplit_k(const float* __restrict__ src, const float* __restrict__ kscale,
                         __nv_bfloat16* __restrict__ dhi, __nv_bfloat16* __restrict__ dlo)
{
    __shared__ float t[32][33];
    int k0 = blockIdx.x*32, n0 = blockIdx.y*32;
    int tx = threadIdx.x, ty = threadIdx.y;
    float w = src[(size_t)(k0+ty)*FF + n0+tx] * kscale[k0+ty];
    t[ty][tx] = w;
    __syncthreads();
    float v = t[tx][ty];
    __nv_bfloat16 h = __float2bfloat16(v);
    dhi[(size_t)(n0+ty)*FF + k0+tx] = h;
    dlo[(size_t)(n0+ty)*FF + k0+tx] = __float2bfloat16(v - __bfloat162float(h));
}

__global__ void fill_biasPQ(const float* __restrict__ b1, float* __restrict__ biasPQ)
{
    int t = threadIdx.x;
    biasPQ[t] = b1[t];
    biasPQ[256+t] = 0.f;
}

__global__ void fold_dbias_k(const float* __restrict__ w1, const float* __restrict__ b1,
                             const float* __restrict__ sh2, float* __restrict__ db)
{
    int c = threadIdx.x;
    float s = b1[c];
    for (int f=0; f<FF; f++) s = fmaf(sh2[f], w1[(size_t)(512+f)*FF + c], s);
    db[c]=s;
}

__global__ void fold_fc_k(const float* __restrict__ fcw, const float* __restrict__ fcb,
                          const float* __restrict__ sc, const float* __restrict__ sh,
                          float* __restrict__ fcw2, float* __restrict__ fcb2)
{
    int t = threadIdx.x;
    fcw2[2*t]   = sc[t]*fcw[2*t];
    fcw2[2*t+1] = sc[t]*fcw[2*t+1];
    if (t < 2){
        float s = fcb[t];
        for (int f=0; f<FF; f++) s = fmaf(sh[f], fcw[2*f+t], s);
        fcb2[t]=s;
    }
}

__global__ void final_out_k(const float* __restrict__ h4, const float* __restrict__ fcw2,
                            const float* __restrict__ fcb2, float* __restrict__ out)
{
    int warpId = threadIdx.x >> 5; int lane = threadIdx.x & 31;
    int row = blockIdx.x*8 + warpId;
    const float* hr = h4 + (size_t)row*FF;
    float s0=0.f, s1=0.f;
    #pragma unroll
    for (int f=lane; f<FF; f+=32){
        float h = hr[f];
        s0 = fmaf(h, fcw2[2*f],   s0);
        s1 = fmaf(h, fcw2[2*f+1], s1);
    }
    #pragma unroll
    for (int o=16;o;o>>=1){
        s0 += __shfl_down_sync(0xffffffffu, s0, o);
        s1 += __shfl_down_sync(0xffffffffu, s1, o);
    }
    if (lane==0){ out[(size_t)row*2]=s0+fcb2[0]; out[(size_t)row*2+1]=s1+fcb2[1]; }
}

// ---------------- host ----------------
extern "C" void kernel_launch(void* const* d_in, const int* in_sizes, int n_in,
                              void* d_out, int out_size)
{
    (void)in_sizes; (void)n_in; (void)out_size;
    const float* inputs = (const float*)d_in[0];
    const float* m1w1=(const float*)d_in[3],  *m1b1=(const float*)d_in[4],
               * m1w2=(const float*)d_in[5],  *m1b2=(const float*)d_in[6],
               * m1g =(const float*)d_in[7],  *m1be=(const float*)d_in[8];
    const float* m2w1=(const float*)d_in[9],  *m2b1=(const float*)d_in[10],
               * m2w2=(const float*)d_in[11], *m2b2=(const float*)d_in[12],
               * m2g =(const float*)d_in[13], *m2be=(const float*)d_in[14];
    const float* m3w1=(const float*)d_in[15], *m3b1=(const float*)d_in[16],
               * m3w2=(const float*)d_in[17], *m3b2=(const float*)d_in[18],
               * m3g =(const float*)d_in[19], *m3be=(const float*)d_in[20];
    const float* m4w1=(const float*)d_in[21], *m4b1=(const float*)d_in[22],
               * m4w2=(const float*)d_in[23], *m4b2=(const float*)d_in[24],
               * m4g =(const float*)d_in[25], *m4be=(const float*)d_in[26];
    const float* fcw =(const float*)d_in[27], *fcb =(const float*)d_in[28];
    float* out = (float*)d_out;

    float *nodeA,*nodeB,*nodeC,*nodeD,*PQ,*SR,*inc,*bigA,*bigB;
    float *psum,*psq,*scale,*shift,*db,*biasPQ,*fcw2,*fcb2;
    __nv_bfloat16 *WL1hi,*WL1lo,*WL2hi,*WL2lo,*WL3hi,*WL3lo,*WL4hi,*WL4lo;
    __nv_bfloat16 *WPQhi,*WPQlo,*WSRhi,*WSRlo,*W2hi,*W2lo,*W4hi,*W4lo,*WSKhi,*WSKlo;
    cudaGetSymbolAddress((void**)&nodeA, g_nodeA);
    cudaGetSymbolAddress((void**)&nodeB, g_nodeB);
    cudaGetSymbolAddress((void**)&nodeC, g_nodeC);
    cudaGetSymbolAddress((void**)&nodeD, g_nodeD);
    cudaGetSymbolAddress((void**)&PQ,    g_PQ);
    cudaGetSymbolAddress((void**)&SR,    g_SR);
    cudaGetSymbolAddress((void**)&inc,   g_inc);
    cudaGetSymbolAddress((void**)&bigA,  g_bigA);
    cudaGetSymbolAddress((void**)&bigB,  g_bigB);
    cudaGetSymbolAddress((void**)&psum,  g_psum);
    cudaGetSymbolAddress((void**)&psq,   g_psq);
    cudaGetSymbolAddress((void**)&scale, g_scale);
    cudaGetSymbolAddress((void**)&shift, g_shift);
    cudaGetSymbolAddress((void**)&db,    g_dbias);
    cudaGetSymbolAddress((void**)&biasPQ,g_biasPQ);
    cudaGetSymbolAddress((void**)&fcw2,  g_fcw2);
    cudaGetSymbolAddress((void**)&fcb2,  g_fcb2);
    cudaGetSymbolAddress((void**)&WL1hi, g_WL1hi); cudaGetSymbolAddress((void**)&WL1lo, g_WL1lo);
    cudaGetSymbolAddress((void**)&WL2hi, g_WL2hi); cudaGetSymbolAddress((void**)&WL2lo, g_WL2lo);
    cudaGetSymbolAddress((void**)&WL3hi, g_WL3hi); cudaGetSymbolAddress((void**)&WL3lo, g_WL3lo);
    cudaGetSymbolAddress((void**)&WL4hi, g_WL4hi); cudaGetSymbolAddress((void**)&WL4lo, g_WL4lo);
    cudaGetSymbolAddress((void**)&WPQhi, g_WPQhi); cudaGetSymbolAddress((void**)&WPQlo, g_WPQlo);
    cudaGetSymbolAddress((void**)&WSRhi, g_WSRhi); cudaGetSymbolAddress((void**)&WSRlo, g_WSRlo);
    cudaGetSymbolAddress((void**)&W2hi,  g_W2hi);  cudaGetSymbolAddress((void**)&W2lo,  g_W2lo);
    cudaGetSymbolAddress((void**)&W4hi,  g_W4hi);  cudaGetSymbolAddress((void**)&W4lo,  g_W4lo);
    cudaGetSymbolAddress((void**)&WSKhi, g_WSKhi); cudaGetSymbolAddress((void**)&WSKlo, g_WSKlo);

    cudaFuncSetAttribute(hgemm2<2,true,true ,false>, cudaFuncAttributeMaxDynamicSharedMemorySize, SMEM_H2);
    cudaFuncSetAttribute(hgemm2<0,true,false,true >, cudaFuncAttributeMaxDynamicSharedMemorySize, SMEM_H2);
    cudaFuncSetAttribute(hgemm2<0,true,true ,false>, cudaFuncAttributeMaxDynamicSharedMemorySize, SMEM_H2);

    TJobs10 J;
    J.j[0] = { m1w1, 0,   WL1hi, WL1lo, 0   };
    J.j[1] = { m1w2, 0,   WL2hi, WL2lo, 0   };
    J.j[2] = { m2w1, 0,   WPQhi, WPQlo, 0   };
    J.j[3] = { m2w1, 256, WPQhi, WPQlo, 256 };
    J.j[4] = { m3w1, 0,   WL3hi, WL3lo, 0   };
    J.j[5] = { m3w2, 0,   WL4hi, WL4lo, 0   };
    J.j[6] = { m4w1, 0,   WSRhi, WSRlo, 0   };
    J.j[7] = { m4w1, 256, WSRhi, WSRlo, 256 };
    J.j[8] = { m2w2, 0,   W2hi,  W2lo,  0   };
    J.j[9] = { m4w2, 0,   W4hi,  W4lo,  0   };
    tsplit_all<<<dim3(8,8,10), dim3(32,32)>>>(J);
    fill_biasPQ<<<1,256>>>(m2b1, biasPQ);

    dim3 gNode(NODE_CH, 2), gPQ(NODE_CH, 4), gBig(BIG_CH, 2);

    // mlp1 (node HMMA)
    ngemm<0,true,false><<<gNode,256>>>(inputs, WL1hi,WL1lo, m1b1, 0,0, FF, nodeA, 0,0);
    ngemm<0,true,true ><<<gNode,256>>>(nodeA , WL2hi,WL2lo, m1b2, 0,0, FF, nodeB, psum,psq);
    finalize_bn<<<8,256>>>(psum,psq,NODE_CH,m1g,m1be,1.f/NODE_M, scale,shift);

    // PQ = BN1(nodeB) @ [W_P | W_Q]
    ngemm<1,false,false><<<gPQ,256>>>(nodeB, WPQhi,WPQlo, biasPQ, scale,shift, 512, PQ, 0,0);

    // big #1: bigA = elu( elu(P[s]+Q[r]) @ W2 + b2 ), stats -> BN2
    hgemm2<2,true,true,false><<<gBig,256,SMEM_H2>>>(PQ, PQ+256, W2hi,W2lo, m2b2, 0,0,0, bigA, psum,psq);
    finalize_bn<<<8,256>>>(psum,psq,BIG_CH,m2g,m2be,1.f/BIG_M, scale+256,shift+256);

    tsplit_k<<<dim3(8,8),dim3(32,32)>>>(m4w1 + 512*FF, scale+256, WSKhi, WSKlo);
    fold_dbias_k<<<1,256>>>(m4w1, m4b1, shift+256, db);

    edge2node_k<<<2048,256>>>(bigA, scale+256, shift+256, inc);

    // mlp3 (node HMMA)
    ngemm<0,true,false><<<gNode,256>>>(inc  , WL3hi,WL3lo, m3b1, 0,0, FF, nodeC, 0,0);
    ngemm<0,true,true ><<<gNode,256>>>(nodeC, WL4hi,WL4lo, m3b2, 0,0, FF, nodeD, psum,psq);
    finalize_bn<<<8,256>>>(psum,psq,NODE_CH,m3g,m3be,1.f/NODE_M, scale+512,shift+512);

    // SR = BN3(nodeD) @ [W_S | W_R]
    ngemm<1,false,false><<<gPQ,256>>>(nodeD, WSRhi,WSRlo, nullptr, scale+512,shift+512, 512, SR, 0,0);

    // big #2: bigB = elu( bigA @ Wskip + S[s] + R[r] + db )
    hgemm2<0,true,false,true><<<gBig,256,SMEM_H2>>>(bigA,0, WSKhi,WSKlo, nullptr, SR, SR+256, db, bigB, 0,0);
    // big #3: bigA = elu( bigB @ W4 + b2 ), stats -> BN4
    hgemm2<0,true,true,false><<<gBig,256,SMEM_H2>>>(bigB,0, W4hi,W4lo, m4b2, 0,0,0, bigA, psum,psq);
    finalize_bn<<<8,256>>>(psum,psq,BIG_CH,m4g,m4be,1.f/BIG_M, scale+768,shift+768);

    fold_fc_k<<<1,256>>>(fcw, fcb, scale+768, shift+768, fcw2, fcb2);
    final_out_k<<<BIG_M/8,256>>>(bigA, fcw2, fcb2, out);
}

// round 15
// speedup vs baseline: 1.2454x; 1.2454x over previous
#include <cuda_runtime.h>
#include <cuda_fp16.h>
#include <cstdint>
#include <math.h>

#define NN 64
#define BB 32
#define EE 4032
#define FF 256
#define BIG_M  (BB*EE)       // 129024
#define NODE_M (BB*NN)       // 2048
#define BIG_CH (BIG_M/128)   // 1008
#define NODE_CH (NODE_M/32)  // 64

// ---------------- scratch ----------------
__device__ float g_nodeA[NODE_M*FF];
__device__ float g_nodeB[NODE_M*FF];
__device__ float g_nodeC[NODE_M*FF];
__device__ float g_nodeD[NODE_M*FF];
__device__ float g_PQ[NODE_M*2*FF];
__device__ float g_SR[NODE_M*2*FF];
__device__ float g_inc[NODE_M*FF];
__device__ float g_bigA[(size_t)BIG_M*FF];
__device__ float g_bigB[(size_t)BIG_M*FF];
__device__ float g_psum[BIG_CH*FF];
__device__ float g_psq[BIG_CH*FF];
__device__ float g_scale[4*FF];
__device__ float g_shift[4*FF];
__device__ float g_dbias[FF];
__device__ float g_biasPQ[2*FF];
__device__ float g_fcw2[2*FF];
__device__ float g_fcb2[2];
// fp16 transposed weights [n][k], k contiguous (single precision level — no lo)
__device__ __half g_WL1[FF*FF], g_WL2[FF*FF], g_WL3[FF*FF], g_WL4[FF*FF];
__device__ __half g_WPQ[2*FF*FF], g_WSR[2*FF*FF];
__device__ __half g_W2[FF*FF], g_W4[FF*FF], g_WSK[FF*FF];

__device__ __forceinline__ float eluf(float x){ return x > 0.f ? x : expm1f(x); }

__device__ __forceinline__ uint32_t smem_u32(const void* p){
    uint32_t a;
    asm("{ .reg .u64 t; cvta.to.shared.u64 t, %1; cvt.u32.u64 %0, t; }" : "=r"(a) : "l"(p));
    return a;
}

#define LDSM4(r0,r1,r2,r3, addr) \
    asm volatile("ldmatrix.sync.aligned.m8n8.x4.shared.b16 {%0,%1,%2,%3}, [%4];" \
        : "=r"(r0),"=r"(r1),"=r"(r2),"=r"(r3) : "r"(addr))

#define MMA4(d, a0,a1,a2,a3, b0,b1) \
    asm volatile("mma.sync.aligned.m16n8k16.row.col.f32.f16.f16.f32 " \
        "{%0,%1,%2,%3},{%4,%5,%6,%7},{%8,%9},{%0,%1,%2,%3};" \
        : "+f"((d)[0]),"+f"((d)[1]),"+f"((d)[2]),"+f"((d)[3]) \
        : "r"(a0),"r"(a1),"r"(a2),"r"(a3),"r"(b0),"r"(b1))

__device__ __forceinline__ uint32_t pk2h(__half a, __half b){
    return (uint32_t)(*(uint16_t*)&a) | ((uint32_t)(*(uint16_t*)&b) << 16);
}
// fp16 two-term split of a pair of fp32 values
__device__ __forceinline__ void split2h(float x, float y, uint32_t& hi, uint32_t& lo){
    __half hx = __float2half(x), hy = __float2half(y);
    __half lx = __float2half(x - __half2float(hx));
    __half ly = __float2half(y - __half2float(hy));
    hi = pk2h(hx, hy);
    lo = pk2h(lx, ly);
}

// big hgemm smem: A hi/lo (fp16 splits) + B single fp16
#define OFF_PO     0
#define OFF_QO     512
#define OFF_AHI    1024
#define OFF_ALO    11264
#define OFF_B      21504
#define OFF_STAGE  1024
#define SMEM_DYN   67072

// ============ big HMMA GEMM: 128 rows x 256 cols per CTA, fp16 2-pass ============
// AMODE 0: A direct fp32; AMODE 2: A[r][k] = elu(A[po]+PB[qo]) (pitch-512 gathers)
// SRE: epilogue adds Sg[po]+Rg[qo]+db
template<int AMODE, bool DOELU, bool STATS, bool SRE>
__global__ __launch_bounds__(512, 1) void hgemm(
    const float* __restrict__ A, const float* __restrict__ PB,
    const __half* __restrict__ W,
    const float* __restrict__ bias,
    const float* __restrict__ Sg, const float* __restrict__ Rg, const float* __restrict__ db,
    float* __restrict__ C, float* __restrict__ pSum, float* __restrict__ pSq)
{
    extern __shared__ __align__(1024) char smem[];
    const uint32_t sb = smem_u32(smem);
    const int tid = threadIdx.x, wid = tid >> 5, l = tid & 31;
    const int rowbase = blockIdx.x * 128;
    int* po = (int*)(smem + OFF_PO);
    int* qo = (int*)(smem + OFF_QO);

    if (AMODE == 2 || SRE) {
        if (tid < 128) {
            int gr = rowbase + tid;
            int b = gr / EE; int e = gr - b*EE;
            int snd = e / 63; int jp = e - snd*63; int rcv = jp + (jp >= snd ? 1 : 0);
            po[tid] = (b*NN + snd)*512;
            qo[tid] = (b*NN + rcv)*512;
        }
        __syncthreads();
    }

    const int m0  = (wid & 3) * 32;
    const int n0w = (wid >> 2) * 64;

    float acc[2][8][4];
    #pragma unroll
    for (int i=0;i<2;i++)
        #pragma unroll
        for (int j=0;j<8;j++)
            #pragma unroll
            for (int q=0;q<4;q++) acc[i][j][q]=0.f;

    const uint32_t aHiBase = sb + OFF_AHI + (uint32_t)((m0 + (l & 15)) * 80 + ((l >> 4) << 4));
    const int bro = (l & 7) + ((l >> 4) << 3);
    const uint32_t bBase = sb + OFF_B + (uint32_t)((n0w + bro) * 80 + ((l & 8) ? 16 : 0));

    const int prow = tid >> 2, pko = (tid & 3) * 8;   // A: 128r x 32k, 8 el/thread
    const int bnr  = tid >> 1, bko = (tid & 1) * 16;  // B: 256n x 32k, 16 fp16/thread

    float4 fa0, fa1, fb0, fb1;
    uint4 bv0, bv1;

    auto loadStage = [&](int ks){
        const int k0 = ks * 32;
        if (AMODE == 2) {
            const float* pa = A  + po[prow] + k0 + pko;
            const float* pb = PB + qo[prow] + k0 + pko;
            fa0 = *(const float4*)pa; fa1 = *(const float4*)(pa+4);
            fb0 = *(const float4*)pb; fb1 = *(const float4*)(pb+4);
        } else {
            const float* pa = A + (size_t)(rowbase+prow)*FF + k0 + pko;
            fa0 = *(const float4*)pa; fa1 = *(const float4*)(pa+4);
        }
        const size_t go = (size_t)bnr*FF + k0 + bko;
        bv0 = *(const uint4*)(W + go); bv1 = *(const uint4*)(W + go + 8);
    };

    loadStage(0);
    for (int ks = 0; ks < 8; ks++) {
        // convert + store A (fp16 split)
        {
            float e8[8];
            if (AMODE == 2) {
                e8[0]=eluf(fa0.x+fb0.x); e8[1]=eluf(fa0.y+fb0.y); e8[2]=eluf(fa0.z+fb0.z); e8[3]=eluf(fa0.w+fb0.w);
                e8[4]=eluf(fa1.x+fb1.x); e8[5]=eluf(fa1.y+fb1.y); e8[6]=eluf(fa1.z+fb1.z); e8[7]=eluf(fa1.w+fb1.w);
            } else {
                e8[0]=fa0.x; e8[1]=fa0.y; e8[2]=fa0.z; e8[3]=fa0.w;
                e8[4]=fa1.x; e8[5]=fa1.y; e8[6]=fa1.z; e8[7]=fa1.w;
            }
            uint32_t hi[4], lo[4];
            #pragma unroll
            for (int q = 0; q < 4; q++) split2h(e8[2*q], e8[2*q+1], hi[q], lo[q]);
            char* ah = smem + OFF_AHI + prow*80 + pko*2;
            char* al = smem + OFF_ALO + prow*80 + pko*2;
            *(uint4*)ah = make_uint4(hi[0],hi[1],hi[2],hi[3]);
            *(uint4*)al = make_uint4(lo[0],lo[1],lo[2],lo[3]);
        }
        // store B
        {
            char* bh = smem + OFF_B + bnr*80 + bko*2;
            *(uint4*)bh = bv0; *(uint4*)(bh+16) = bv1;
        }
        __syncthreads();
        if (ks < 7) loadStage(ks + 1);   // gmem prefetch behind MMAs

        #pragma unroll
        for (int ksub = 0; ksub < 2; ksub++) {
            uint32_t ah[2][4], alr[2][4];
            #pragma unroll
            for (int mt = 0; mt < 2; mt++) {
                uint32_t ad = aHiBase + (uint32_t)(mt*16*80 + ksub*32);
                LDSM4(ah[mt][0],ah[mt][1],ah[mt][2],ah[mt][3], ad);
                LDSM4(alr[mt][0],alr[mt][1],alr[mt][2],alr[mt][3], ad + (OFF_ALO-OFF_AHI));
            }
            // B-fragment pipeline
            uint32_t bc[4], bn_[4];
            {
                uint32_t bd = bBase + (uint32_t)(ksub*32);
                LDSM4(bc[0],bc[1],bc[2],bc[3], bd);
            }
            #pragma unroll
            for (int nt2 = 0; nt2 < 4; nt2++) {
                if (nt2 < 3) {
                    uint32_t bd = bBase + (uint32_t)((nt2+1)*16*80 + ksub*32);
                    LDSM4(bn_[0],bn_[1],bn_[2],bn_[3], bd);
                }
                #pragma unroll
                for (int mt = 0; mt < 2; mt++) {
                    #pragma unroll
                    for (int t = 0; t < 2; t++) {
                        float* d = acc[mt][nt2*2+t];
                        MMA4(d, ah[mt][0],ah[mt][1],ah[mt][2],ah[mt][3],   bc[t*2], bc[t*2+1]);
                        MMA4(d, alr[mt][0],alr[mt][1],alr[mt][2],alr[mt][3], bc[t*2], bc[t*2+1]);
                    }
                }
                #pragma unroll
                for (int q = 0; q < 4; q++) bc[q] = bn_[q];
            }
        }
        __syncthreads();
    }

    // ---- epilogue in two 128-col halves via SMEM stage ----
    float* stage = (float*)(smem + OFF_STAGE);
    float sS[8], sQ2[8];
    #pragma unroll
    for (int g = 0; g < 8; g++){ sS[g]=0.f; sQ2[g]=0.f; }

    for (int h = 0; h < 2; h++) {
        if ((n0w >> 7) == h) {
            int nl = n0w & 127;
            #pragma unroll
            for (int mt = 0; mt < 2; mt++) {
                #pragma unroll
                for (int nt = 0; nt < 8; nt++) {
                    int r = m0 + mt*16 + (l >> 2);
                    int c = nl + nt*8 + (l & 3)*2;
                    stage[r*129 + c]       = acc[mt][nt][0];
                    stage[r*129 + c + 1]   = acc[mt][nt][1];
                    stage[(r+8)*129 + c]   = acc[mt][nt][2];
                    stage[(r+8)*129 + c+1] = acc[mt][nt][3];
                }
            }
        }
        __syncthreads();
        #pragma unroll
        for (int rr = 0; rr < 8; rr++) {
            int r = wid*8 + rr;
            float* cp = C + (size_t)(rowbase + r)*FF + h*128;
            const float* srP = nullptr; const float* srQ = nullptr;
            if (SRE) { srP = Sg + po[r] + h*128; srQ = Rg + qo[r] + h*128; }
            #pragma unroll
            for (int g = 0; g < 4; g++) {
                int c = g*32 + l;
                float f = stage[r*129 + c];
                if (bias) f += bias[h*128 + c];
                if (SRE)  f += srP[c] + srQ[c] + db[h*128 + c];
                if (DOELU) f = eluf(f);
                cp[c] = f;
                if (STATS) { int s = h*4+g; sS[s] += f; sQ2[s] = fmaf(f, f, sQ2[s]); }
            }
        }
        __syncthreads();
    }

    if (STATS) {
        float* xs = stage;
        float* xq = stage + 4096;
        #pragma unroll
        for (int s = 0; s < 8; s++) {
            int c = (s>>2)*128 + (s&3)*32 + l;
            xs[wid*256 + c] = sS[s];
            xq[wid*256 + c] = sQ2[s];
        }
        __syncthreads();
        if (tid < 256) {
            float s=0.f, q=0.f;
            #pragma unroll
            for (int w = 0; w < 16; w++){ s += xs[w*256 + tid]; q += xq[w*256 + tid]; }
            pSum[(size_t)blockIdx.x*FF + tid] = s;
            pSq [(size_t)blockIdx.x*FF + tid] = q;
        }
    }
}

// ============ node HMMA GEMM: 32 rows x 128 cols per CTA, fp16 2-pass ============
#define N_AHI 0
#define N_ALO 2560
#define N_B   5120
#define N_SMEM 25600
template<int AMODE, bool DOELU, bool STATS>
__global__ __launch_bounds__(256) void ngemm(
    const float* __restrict__ A,
    const __half* __restrict__ W,
    const float* __restrict__ bias,
    const float* __restrict__ aSc, const float* __restrict__ aSh,
    int ldc,
    float* __restrict__ C, float* __restrict__ pSum, float* __restrict__ pSq)
{
    __shared__ __align__(1024) char smem[N_SMEM];
    const uint32_t sb = smem_u32(smem);
    const int tid = threadIdx.x, wid = tid >> 5, l = tid & 31;
    const int rowbase = blockIdx.x * 32;
    const int cb = blockIdx.y * 128;

    const int m0  = (wid & 1) * 16;
    const int n0w = (wid >> 1) * 32;

    float acc[4][4];
    #pragma unroll
    for (int j=0;j<4;j++)
        #pragma unroll
        for (int q=0;q<4;q++) acc[j][q]=0.f;

    const uint32_t aHiBase = sb + N_AHI + (uint32_t)((m0 + (l & 15)) * 80 + ((l >> 4) << 4));
    const int bro = (l & 7) + ((l >> 4) << 3);
    const uint32_t bBase = sb + N_B + (uint32_t)((n0w + bro) * 80 + ((l & 8) ? 16 : 0));

    const int prow = tid >> 3, pko = (tid & 7) * 4;
    const int bnr  = tid >> 1, bko = (tid & 1) * 16;

    float4 fa;
    uint4 bv0, bv1;
    auto loadStage = [&](int ks){
        const int k0 = ks * 32;
        fa = *(const float4*)(A + (size_t)(rowbase+prow)*FF + k0 + pko);
        if (AMODE == 1) {
            const float4 sc = *(const float4*)(aSc + k0 + pko);
            const float4 sh = *(const float4*)(aSh + k0 + pko);
            fa.x = fmaf(sc.x, fa.x, sh.x); fa.y = fmaf(sc.y, fa.y, sh.y);
            fa.z = fmaf(sc.z, fa.z, sh.z); fa.w = fmaf(sc.w, fa.w, sh.w);
        }
        const size_t go = (size_t)(cb + bnr)*FF + k0 + bko;
        bv0 = *(const uint4*)(W + go); bv1 = *(const uint4*)(W + go + 8);
    };

    loadStage(0);
    for (int ks = 0; ks < 8; ks++) {
        {
            uint32_t h0, l0, h1, l1;
            split2h(fa.x, fa.y, h0, l0);
            split2h(fa.z, fa.w, h1, l1);
            char* ah = smem + N_AHI + prow*80 + pko*2;
            char* al = smem + N_ALO + prow*80 + pko*2;
            *(uint2*)ah = make_uint2(h0, h1);
            *(uint2*)al = make_uint2(l0, l1);
        }
        {
            char* bh = smem + N_B + bnr*80 + bko*2;
            *(uint4*)bh = bv0; *(uint4*)(bh+16) = bv1;
        }
        __syncthreads();
        if (ks < 7) loadStage(ks + 1);

        #pragma unroll
        for (int ksub = 0; ksub < 2; ksub++) {
            uint32_t ah[4], alr[4];
            uint32_t ad = aHiBase + (uint32_t)(ksub*32);
            LDSM4(ah[0],ah[1],ah[2],ah[3], ad);
            LDSM4(alr[0],alr[1],alr[2],alr[3], ad + (N_ALO-N_AHI));
            uint32_t bc[4], bn_[4];
            {
                uint32_t bd = bBase + (uint32_t)(ksub*32);
                LDSM4(bc[0],bc[1],bc[2],bc[3], bd);
            }
            #pragma unroll
            for (int nt2 = 0; nt2 < 2; nt2++) {
                if (nt2 < 1) {
                    uint32_t bd = bBase + (uint32_t)(16*80 + ksub*32);
                    LDSM4(bn_[0],bn_[1],bn_[2],bn_[3], bd);
                }
                #pragma unroll
                for (int t = 0; t < 2; t++) {
                    float* d = acc[nt2*2+t];
                    MMA4(d, ah[0],ah[1],ah[2],ah[3],   bc[t*2], bc[t*2+1]);
                    MMA4(d, alr[0],alr[1],alr[2],alr[3], bc[t*2], bc[t*2+1]);
                }
                #pragma unroll
                for (int q = 0; q < 4; q++) bc[q] = bn_[q];
            }
        }
        __syncthreads();
    }

    float* stage = (float*)smem;
    #pragma unroll
    for (int nt = 0; nt < 4; nt++) {
        int r = m0 + (l >> 2);
        int c = n0w + nt*8 + (l & 3)*2;
        stage[r*129 + c]       = acc[nt][0];
        stage[r*129 + c + 1]   = acc[nt][1];
        stage[(r+8)*129 + c]   = acc[nt][2];
        stage[(r+8)*129 + c+1] = acc[nt][3];
    }
    __syncthreads();

    float sS[4], sQ2[4];
    #pragma unroll
    for (int g = 0; g < 4; g++){ sS[g]=0.f; sQ2[g]=0.f; }
    #pragma unroll
    for (int rr = 0; rr < 4; rr++) {
        int r = wid*4 + rr;
        float* cp = C + (size_t)(rowbase + r)*ldc + cb;
        #pragma unroll
        for (int g = 0; g < 4; g++) {
            int c = g*32 + l;
            float f = stage[r*129 + c];
            if (bias) f += bias[cb + c];
            if (DOELU) f = eluf(f);
            cp[c] = f;
            if (STATS) { sS[g] += f; sQ2[g] = fmaf(f, f, sQ2[g]); }
        }
    }
    if (STATS) {
        __syncthreads();
        float* xs = (float*)(smem + 16512);
        float* xq = (float*)(smem + 20608);
        #pragma unroll
        for (int g = 0; g < 4; g++) {
            xs[wid*128 + g*32 + l] = sS[g];
            xq[wid*128 + g*32 + l] = sQ2[g];
        }
        __syncthreads();
        if (tid < 128) {
            float s=0.f, q=0.f;
            #pragma unroll
            for (int w = 0; w < 8; w++){ s += xs[w*128 + tid]; q += xq[w*128 + tid]; }
            pSum[(size_t)blockIdx.x*FF + cb + tid] = s;
            pSq [(size_t)blockIdx.x*FF + cb + tid] = q;
        }
    }
}

// ---------------- small kernels ----------------
__global__ void finalize_bn(const float* __restrict__ pSum, const float* __restrict__ pSq,
                            int nchunks, const float* __restrict__ g, const float* __restrict__ beta,
                            float invM, float* __restrict__ sc, float* __restrict__ sh)
{
    __shared__ float rs[256], rq[256];
    int lane = threadIdx.x & 31, part = threadIdx.x >> 5;
    int f = blockIdx.x*32 + lane;
    float s=0.f, q=0.f;
    for (int c=part; c<nchunks; c+=8){ s += pSum[(size_t)c*FF+f]; q += pSq[(size_t)c*FF+f]; }
    rs[threadIdx.x]=s; rq[threadIdx.x]=q;
    __syncthreads();
    if (part == 0){
        #pragma unroll
        for (int w=1; w<8; w++){ s += rs[w*32+lane]; q += rq[w*32+lane]; }
        float mean = s*invM;
        float var  = fmaf(-mean, mean, q*invM);
        float a = g[f]*rsqrtf(var + 1e-5f);
        sc[f]=a; sh[f] = fmaf(-mean, a, beta[f]);
    }
}

__global__ void edge2node_k(const float* __restrict__ h2, const float* __restrict__ sc,
                            const float* __restrict__ sh, float* __restrict__ inc)
{
    int bn = blockIdx.x; int b = bn >> 6; int n = bn & 63; int f = threadIdx.x;
    const float* base = h2 + (size_t)b*EE*FF + f;
    float s = 0.f;
    #pragma unroll
    for (int j=0;j<NN;j++){
        if (j==n) continue;
        int e = j*63 + (j < n ? n-1 : n);
        s += base[(size_t)e*FF];
    }
    inc[(size_t)bn*FF+f] = (sc[f]*s + 63.f*sh[f]) * (1.f/64.f);
}

// batched transpose + fp16 convert: dst[dstOff+n][k] = fp16(src[srcOff+k][n])
struct TJob { const float* src; int srcOff; __half* dst; int dstOff; };
struct TJobs10 { TJob j[10]; };
__global__ void thalf_all(TJobs10 P)
{
    __shared__ float t[32][33];
    TJob jb = P.j[blockIdx.z];
    int k0 = blockIdx.x*32, n0 = blockIdx.y*32;
    int tx = threadIdx.x, ty = threadIdx.y;
    t[ty][tx] = jb.src[(size_t)(jb.srcOff + k0+ty)*FF + n0+tx];
    __syncthreads();
    jb.dst[(size_t)(jb.dstOff + n0+ty)*FF + k0+tx] = __float2half(t[tx][ty]);
}

// runtime fold: dst[n][k] = fp16(src[k][n] * kscale[k])
__global__ void thalf_k(const float* __restrict__ src, const float* __restrict__ kscale,
                        __half* __restrict__ dst)
{
    __shared__ float t[32][33];
    int k0 = blockIdx.x*32, n0 = blockIdx.y*32;
    int tx = threadIdx.x, ty = threadIdx.y;
    t[ty][tx] = src[(size_t)(k0+ty)*FF + n0+tx] * kscale[k0+ty];
    __syncthreads();
    dst[(size_t)(n0+ty)*FF + k0+tx] = __float2half(t[tx][ty]);
}

__global__ void fill_biasPQ(const float* __restrict__ b1, float* __restrict__ biasPQ)
{
    int t = threadIdx.x;
    biasPQ[t] = b1[t];
    biasPQ[256+t] = 0.f;
}

__global__ void fold_dbias_k(const float* __restrict__ w1, const float* __restrict__ b1,
                             const float* __restrict__ sh2, float* __restrict__ db)
{
    int c = threadIdx.x;
    float s = b1[c];
    for (int f=0; f<FF; f++) s = fmaf(sh2[f], w1[(size_t)(512+f)*FF + c], s);
    db[c]=s;
}

__global__ void fold_fc_k(const float* __restrict__ fcw, const float* __restrict__ fcb,
                          const float* __restrict__ sc, const float* __restrict__ sh,
                          float* __restrict__ fcw2, float* __restrict__ fcb2)
{
    int t = threadIdx.x;
    fcw2[2*t]   = sc[t]*fcw[2*t];
    fcw2[2*t+1] = sc[t]*fcw[2*t+1];
    if (t < 2){
        float s = fcb[t];
        for (int f=0; f<FF; f++) s = fmaf(sh[f], fcw[2*f+t], s);
        fcb2[t]=s;
    }
}

__global__ void final_out_k(const float* __restrict__ h4, const float* __restrict__ fcw2,
                            const float* __restrict__ fcb2, float* __restrict__ out)
{
    int warpId = threadIdx.x >> 5; int lane = threadIdx.x & 31;
    int row = blockIdx.x*8 + warpId;
    const float* hr = h4 + (size_t)row*FF;
    float s0=0.f, s1=0.f;
    #pragma unroll
    for (int f=lane; f<FF; f+=32){
        float h = hr[f];
        s0 = fmaf(h, fcw2[2*f],   s0);
        s1 = fmaf(h, fcw2[2*f+1], s1);
    }
    #pragma unroll
    for (int o=16;o;o>>=1){
        s0 += __shfl_down_sync(0xffffffffu, s0, o);
        s1 += __shfl_down_sync(0xffffffffu, s1, o);
    }
    if (lane==0){ out[(size_t)row*2]=s0+fcb2[0]; out[(size_t)row*2+1]=s1+fcb2[1]; }
}

// ---------------- host ----------------
extern "C" void kernel_launch(void* const* d_in, const int* in_sizes, int n_in,
                              void* d_out, int out_size)
{
    (void)in_sizes; (void)n_in; (void)out_size;
    const float* inputs = (const float*)d_in[0];
    const float* m1w1=(const float*)d_in[3],  *m1b1=(const float*)d_in[4],
               * m1w2=(const float*)d_in[5],  *m1b2=(const float*)d_in[6],
               * m1g =(const float*)d_in[7],  *m1be=(const float*)d_in[8];
    const float* m2w1=(const float*)d_in[9],  *m2b1=(const float*)d_in[10],
               * m2w2=(const float*)d_in[11], *m2b2=(const float*)d_in[12],
               * m2g =(const float*)d_in[13], *m2be=(const float*)d_in[14];
    const float* m3w1=(const float*)d_in[15], *m3b1=(const float*)d_in[16],
               * m3w2=(const float*)d_in[17], *m3b2=(const float*)d_in[18],
               * m3g =(const float*)d_in[19], *m3be=(const float*)d_in[20];
    const float* m4w1=(const float*)d_in[21], *m4b1=(const float*)d_in[22],
               * m4w2=(const float*)d_in[23], *m4b2=(const float*)d_in[24],
               * m4g =(const float*)d_in[25], *m4be=(const float*)d_in[26];
    const float* fcw =(const float*)d_in[27], *fcb =(const float*)d_in[28];
    float* out = (float*)d_out;

    float *nodeA,*nodeB,*nodeC,*nodeD,*PQ,*SR,*inc,*bigA,*bigB;
    float *psum,*psq,*scale,*shift,*db,*biasPQ,*fcw2,*fcb2;
    __half *WL1,*WL2,*WL3,*WL4,*WPQ,*WSR,*W2,*W4,*WSK;
    cudaGetSymbolAddress((void**)&nodeA, g_nodeA);
    cudaGetSymbolAddress((void**)&nodeB, g_nodeB);
    cudaGetSymbolAddress((void**)&nodeC, g_nodeC);
    cudaGetSymbolAddress((void**)&nodeD, g_nodeD);
    cudaGetSymbolAddress((void**)&PQ,    g_PQ);
    cudaGetSymbolAddress((void**)&SR,    g_SR);
    cudaGetSymbolAddress((void**)&inc,   g_inc);
    cudaGetSymbolAddress((void**)&bigA,  g_bigA);
    cudaGetSymbolAddress((void**)&bigB,  g_bigB);
    cudaGetSymbolAddress((void**)&psum,  g_psum);
    cudaGetSymbolAddress((void**)&psq,   g_psq);
    cudaGetSymbolAddress((void**)&scale, g_scale);
    cudaGetSymbolAddress((void**)&shift, g_shift);
    cudaGetSymbolAddress((void**)&db,    g_dbias);
    cudaGetSymbolAddress((void**)&biasPQ,g_biasPQ);
    cudaGetSymbolAddress((void**)&fcw2,  g_fcw2);
    cudaGetSymbolAddress((void**)&fcb2,  g_fcb2);
    cudaGetSymbolAddress((void**)&WL1,   g_WL1);
    cudaGetSymbolAddress((void**)&WL2,   g_WL2);
    cudaGetSymbolAddress((void**)&WL3,   g_WL3);
    cudaGetSymbolAddress((void**)&WL4,   g_WL4);
    cudaGetSymbolAddress((void**)&WPQ,   g_WPQ);
    cudaGetSymbolAddress((void**)&WSR,   g_WSR);
    cudaGetSymbolAddress((void**)&W2,    g_W2);
    cudaGetSymbolAddress((void**)&W4,    g_W4);
    cudaGetSymbolAddress((void**)&WSK,   g_WSK);

    cudaFuncSetAttribute(hgemm<2,true,true ,false>, cudaFuncAttributeMaxDynamicSharedMemorySize, SMEM_DYN);
    cudaFuncSetAttribute(hgemm<0,true,false,true >, cudaFuncAttributeMaxDynamicSharedMemorySize, SMEM_DYN);
    cudaFuncSetAttribute(hgemm<0,true,true ,false>, cudaFuncAttributeMaxDynamicSharedMemorySize, SMEM_DYN);

    TJobs10 J;
    J.j[0] = { m1w1, 0,   WL1, 0   };
    J.j[1] = { m1w2, 0,   WL2, 0   };
    J.j[2] = { m2w1, 0,   WPQ, 0   };
    J.j[3] = { m2w1, 256, WPQ, 256 };
    J.j[4] = { m3w1, 0,   WL3, 0   };
    J.j[5] = { m3w2, 0,   WL4, 0   };
    J.j[6] = { m4w1, 0,   WSR, 0   };
    J.j[7] = { m4w1, 256, WSR, 256 };
    J.j[8] = { m2w2, 0,   W2,  0   };
    J.j[9] = { m4w2, 0,   W4,  0   };
    thalf_all<<<dim3(8,8,10), dim3(32,32)>>>(J);
    fill_biasPQ<<<1,256>>>(m2b1, biasPQ);

    dim3 gNode(NODE_CH, 2), gPQ(NODE_CH, 4), gBig(BIG_CH, 1);

    // mlp1 (node HMMA)
    ngemm<0,true,false><<<gNode,256>>>(inputs, WL1, m1b1, 0,0, FF, nodeA, 0,0);
    ngemm<0,true,true ><<<gNode,256>>>(nodeA , WL2, m1b2, 0,0, FF, nodeB, psum,psq);
    finalize_bn<<<8,256>>>(psum,psq,NODE_CH,m1g,m1be,1.f/NODE_M, scale,shift);

    // PQ = BN1(nodeB) @ [W_P | W_Q]
    ngemm<1,false,false><<<gPQ,256>>>(nodeB, WPQ, biasPQ, scale,shift, 512, PQ, 0,0);

    // big #1: bigA = elu( elu(P[s]+Q[r]) @ W2 + b2 ), stats -> BN2
    hgemm<2,true,true,false><<<gBig,512,SMEM_DYN>>>(PQ, PQ+256, W2, m2b2, 0,0,0, bigA, psum,psq);
    finalize_bn<<<8,256>>>(psum,psq,BIG_CH,m2g,m2be,1.f/BIG_M, scale+256,shift+256);

    thalf_k<<<dim3(8,8),dim3(32,32)>>>(m4w1 + 512*FF, scale+256, WSK);
    fold_dbias_k<<<1,256>>>(m4w1, m4b1, shift+256, db);

    edge2node_k<<<2048,256>>>(bigA, scale+256, shift+256, inc);

    // mlp3 (node HMMA)
    ngemm<0,true,false><<<gNode,256>>>(inc  , WL3, m3b1, 0,0, FF, nodeC, 0,0);
    ngemm<0,true,true ><<<gNode,256>>>(nodeC, WL4, m3b2, 0,0, FF, nodeD, psum,psq);
    finalize_bn<<<8,256>>>(psum,psq,NODE_CH,m3g,m3be,1.f/NODE_M, scale+512,shift+512);

    // SR = BN3(nodeD) @ [W_S | W_R]
    ngemm<1,false,false><<<gPQ,256>>>(nodeD, WSR, nullptr, scale+512,shift+512, 512, SR, 0,0);

    // big #2: bigB = elu( bigA @ Wskip + S[s] + R[r] + db )
    hgemm<0,true,false,true><<<gBig,512,SMEM_DYN>>>(bigA,0, WSK, nullptr, SR, SR+256, db, bigB, 0,0);
    // big #3: bigA = elu( bigB @ W4 + b2 ), stats -> BN4
    hgemm<0,true,true,false><<<gBig,512,SMEM_DYN>>>(bigB,0, W4, m4b2, 0,0,0, bigA, psum,psq);
    finalize_bn<<<8,256>>>(psum,psq,BIG_CH,m4g,m4be,1.f/BIG_M, scale+768,shift+768);

    fold_fc_k<<<1,256>>>(fcw, fcb, scale+768, shift+768, fcw2, fcb2);
    final_out_k<<<BIG_M/8,256>>>(bigA, fcw2, fcb2, out);
}

// round 16
// speedup vs baseline: 1.2475x; 1.0017x over previous
#include <cuda_runtime.h>
#include <cuda_fp16.h>
#include <cstdint>
#include <math.h>

#define NN 64
#define BB 32
#define EE 4032
#define FF 256
#define BIG_M  (BB*EE)       // 129024
#define NODE_M (BB*NN)       // 2048
#define BIG_CH (BIG_M/128)   // 1008
#define NODE_CH (NODE_M/32)  // 64

// ---------------- scratch ----------------
__device__ float g_nodeA[NODE_M*FF];
__device__ float g_nodeB[NODE_M*FF];
__device__ float g_nodeC[NODE_M*FF];
__device__ float g_nodeD[NODE_M*FF];
__device__ float g_PQ[NODE_M*2*FF];
__device__ float g_SR[NODE_M*2*FF];
__device__ float g_inc[NODE_M*FF];
__device__ float g_bigA[(size_t)BIG_M*FF];
__device__ float g_bigB[(size_t)BIG_M*FF];
__device__ float g_psum[BIG_CH*FF];
__device__ float g_psq[BIG_CH*FF];
__device__ float g_scale[4*FF];
__device__ float g_shift[4*FF];
__device__ float g_dbias[FF];
__device__ float g_biasPQ[2*FF];
__device__ float g_fcw2[2*FF];
__device__ float g_fcb2[2];
__device__ __half g_WL1[FF*FF], g_WL2[FF*FF], g_WL3[FF*FF], g_WL4[FF*FF];
__device__ __half g_WPQ[2*FF*FF], g_WSR[2*FF*FF];
__device__ __half g_W2[FF*FF], g_W4[FF*FF], g_WSK[FF*FF];

__device__ __forceinline__ float eluf(float x){ return x > 0.f ? x : expm1f(x); }

__device__ __forceinline__ uint32_t smem_u32(const void* p){
    uint32_t a;
    asm("{ .reg .u64 t; cvta.to.shared.u64 t, %1; cvt.u32.u64 %0, t; }" : "=r"(a) : "l"(p));
    return a;
}

#define LDSM4(r0,r1,r2,r3, addr) \
    asm volatile("ldmatrix.sync.aligned.m8n8.x4.shared.b16 {%0,%1,%2,%3}, [%4];" \
        : "=r"(r0),"=r"(r1),"=r"(r2),"=r"(r3) : "r"(addr))

#define MMA4(d, a0,a1,a2,a3, b0,b1) \
    asm volatile("mma.sync.aligned.m16n8k16.row.col.f32.f16.f16.f32 " \
        "{%0,%1,%2,%3},{%4,%5,%6,%7},{%8,%9},{%0,%1,%2,%3};" \
        : "+f"((d)[0]),"+f"((d)[1]),"+f"((d)[2]),"+f"((d)[3]) \
        : "r"(a0),"r"(a1),"r"(a2),"r"(a3),"r"(b0),"r"(b1))

__device__ __forceinline__ uint32_t pk2h(__half a, __half b){
    return (uint32_t)(*(uint16_t*)&a) | ((uint32_t)(*(uint16_t*)&b) << 16);
}
__device__ __forceinline__ void split2h(float x, float y, uint32_t& hi, uint32_t& lo){
    __half hx = __float2half(x), hy = __float2half(y);
    __half lx = __float2half(x - __half2float(hx));
    __half ly = __float2half(y - __half2float(hy));
    hi = pk2h(hx, hy);
    lo = pk2h(lx, ly);
}

// big hgemm smem: A hi/lo (fp16 splits) + B single fp16  (R15 proven — unchanged)
#define OFF_PO     0
#define OFF_QO     512
#define OFF_AHI    1024
#define OFF_ALO    11264
#define OFF_B      21504
#define OFF_STAGE  1024
#define SMEM_DYN   67072

// ============ big HMMA GEMM: 128 rows x 256 cols per CTA, fp16 2-pass ============
template<int AMODE, bool DOELU, bool STATS, bool SRE>
__global__ __launch_bounds__(512, 1) void hgemm(
    const float* __restrict__ A, const float* __restrict__ PB,
    const __half* __restrict__ W,
    const float* __restrict__ bias,
    const float* __restrict__ Sg, const float* __restrict__ Rg, const float* __restrict__ db,
    float* __restrict__ C, float* __restrict__ pSum, float* __restrict__ pSq)
{
    extern __shared__ __align__(1024) char smem[];
    const uint32_t sb = smem_u32(smem);
    const int tid = threadIdx.x, wid = tid >> 5, l = tid & 31;
    const int rowbase = blockIdx.x * 128;
    int* po = (int*)(smem + OFF_PO);
    int* qo = (int*)(smem + OFF_QO);

    if (AMODE == 2 || SRE) {
        if (tid < 128) {
            int gr = rowbase + tid;
            int b = gr / EE; int e = gr - b*EE;
            int snd = e / 63; int jp = e - snd*63; int rcv = jp + (jp >= snd ? 1 : 0);
            po[tid] = (b*NN + snd)*512;
            qo[tid] = (b*NN + rcv)*512;
        }
        __syncthreads();
    }

    const int m0  = (wid & 3) * 32;
    const int n0w = (wid >> 2) * 64;

    float acc[2][8][4];
    #pragma unroll
    for (int i=0;i<2;i++)
        #pragma unroll
        for (int j=0;j<8;j++)
            #pragma unroll
            for (int q=0;q<4;q++) acc[i][j][q]=0.f;

    const uint32_t aHiBase = sb + OFF_AHI + (uint32_t)((m0 + (l & 15)) * 80 + ((l >> 4) << 4));
    const int bro = (l & 7) + ((l >> 4) << 3);
    const uint32_t bBase = sb + OFF_B + (uint32_t)((n0w + bro) * 80 + ((l & 8) ? 16 : 0));

    const int prow = tid >> 2, pko = (tid & 3) * 8;
    const int bnr  = tid >> 1, bko = (tid & 1) * 16;

    float4 fa0, fa1, fb0, fb1;
    uint4 bv0, bv1;

    auto loadStage = [&](int ks){
        const int k0 = ks * 32;
        if (AMODE == 2) {
            const float* pa = A  + po[prow] + k0 + pko;
            const float* pb = PB + qo[prow] + k0 + pko;
            fa0 = *(const float4*)pa; fa1 = *(const float4*)(pa+4);
            fb0 = *(const float4*)pb; fb1 = *(const float4*)(pb+4);
        } else {
            const float* pa = A + (size_t)(rowbase+prow)*FF + k0 + pko;
            fa0 = *(const float4*)pa; fa1 = *(const float4*)(pa+4);
        }
        const size_t go = (size_t)bnr*FF + k0 + bko;
        bv0 = *(const uint4*)(W + go); bv1 = *(const uint4*)(W + go + 8);
    };

    loadStage(0);
    for (int ks = 0; ks < 8; ks++) {
        {
            float e8[8];
            if (AMODE == 2) {
                e8[0]=eluf(fa0.x+fb0.x); e8[1]=eluf(fa0.y+fb0.y); e8[2]=eluf(fa0.z+fb0.z); e8[3]=eluf(fa0.w+fb0.w);
                e8[4]=eluf(fa1.x+fb1.x); e8[5]=eluf(fa1.y+fb1.y); e8[6]=eluf(fa1.z+fb1.z); e8[7]=eluf(fa1.w+fb1.w);
            } else {
                e8[0]=fa0.x; e8[1]=fa0.y; e8[2]=fa0.z; e8[3]=fa0.w;
                e8[4]=fa1.x; e8[5]=fa1.y; e8[6]=fa1.z; e8[7]=fa1.w;
            }
            uint32_t hi[4], lo[4];
            #pragma unroll
            for (int q = 0; q < 4; q++) split2h(e8[2*q], e8[2*q+1], hi[q], lo[q]);
            char* ah = smem + OFF_AHI + prow*80 + pko*2;
            char* al = smem + OFF_ALO + prow*80 + pko*2;
            *(uint4*)ah = make_uint4(hi[0],hi[1],hi[2],hi[3]);
            *(uint4*)al = make_uint4(lo[0],lo[1],lo[2],lo[3]);
        }
        {
            char* bh = smem + OFF_B + bnr*80 + bko*2;
            *(uint4*)bh = bv0; *(uint4*)(bh+16) = bv1;
        }
        __syncthreads();
        if (ks < 7) loadStage(ks + 1);

        #pragma unroll
        for (int ksub = 0; ksub < 2; ksub++) {
            uint32_t ah[2][4], alr[2][4];
            #pragma unroll
            for (int mt = 0; mt < 2; mt++) {
                uint32_t ad = aHiBase + (uint32_t)(mt*16*80 + ksub*32);
                LDSM4(ah[mt][0],ah[mt][1],ah[mt][2],ah[mt][3], ad);
                LDSM4(alr[mt][0],alr[mt][1],alr[mt][2],alr[mt][3], ad + (OFF_ALO-OFF_AHI));
            }
            uint32_t bc[4], bn_[4];
            {
                uint32_t bd = bBase + (uint32_t)(ksub*32);
                LDSM4(bc[0],bc[1],bc[2],bc[3], bd);
            }
            #pragma unroll
            for (int nt2 = 0; nt2 < 4; nt2++) {
                if (nt2 < 3) {
                    uint32_t bd = bBase + (uint32_t)((nt2+1)*16*80 + ksub*32);
                    LDSM4(bn_[0],bn_[1],bn_[2],bn_[3], bd);
                }
                #pragma unroll
                for (int mt = 0; mt < 2; mt++) {
                    #pragma unroll
                    for (int t = 0; t < 2; t++) {
                        float* d = acc[mt][nt2*2+t];
                        MMA4(d, ah[mt][0],ah[mt][1],ah[mt][2],ah[mt][3],   bc[t*2], bc[t*2+1]);
                        MMA4(d, alr[mt][0],alr[mt][1],alr[mt][2],alr[mt][3], bc[t*2], bc[t*2+1]);
                    }
                }
                #pragma unroll
                for (int q = 0; q < 4; q++) bc[q] = bn_[q];
            }
        }
        __syncthreads();
    }

    // ---- epilogue in two 128-col halves via SMEM stage ----
    float* stage = (float*)(smem + OFF_STAGE);
    float sS[8], sQ2[8];
    #pragma unroll
    for (int g = 0; g < 8; g++){ sS[g]=0.f; sQ2[g]=0.f; }

    for (int h = 0; h < 2; h++) {
        if ((n0w >> 7) == h) {
            int nl = n0w & 127;
            #pragma unroll
            for (int mt = 0; mt < 2; mt++) {
                #pragma unroll
                for (int nt = 0; nt < 8; nt++) {
                    int r = m0 + mt*16 + (l >> 2);
                    int c = nl + nt*8 + (l & 3)*2;
                    stage[r*129 + c]       = acc[mt][nt][0];
                    stage[r*129 + c + 1]   = acc[mt][nt][1];
                    stage[(r+8)*129 + c]   = acc[mt][nt][2];
                    stage[(r+8)*129 + c+1] = acc[mt][nt][3];
                }
            }
        }
        __syncthreads();
        #pragma unroll
        for (int rr = 0; rr < 8; rr++) {
            int r = wid*8 + rr;
            float* cp = C + (size_t)(rowbase + r)*FF + h*128;
            const float* srP = nullptr; const float* srQ = nullptr;
            if (SRE) { srP = Sg + po[r] + h*128; srQ = Rg + qo[r] + h*128; }
            #pragma unroll
            for (int g = 0; g < 4; g++) {
                int c = g*32 + l;
                float f = stage[r*129 + c];
                if (bias) f += bias[h*128 + c];
                if (SRE)  f += srP[c] + srQ[c] + db[h*128 + c];
                if (DOELU) f = eluf(f);
                cp[c] = f;
                if (STATS) { int s = h*4+g; sS[s] += f; sQ2[s] = fmaf(f, f, sQ2[s]); }
            }
        }
        __syncthreads();
    }

    if (STATS) {
        float* xs = stage;
        float* xq = stage + 4096;
        #pragma unroll
        for (int s = 0; s < 8; s++) {
            int c = (s>>2)*128 + (s&3)*32 + l;
            xs[wid*256 + c] = sS[s];
            xq[wid*256 + c] = sQ2[s];
        }
        __syncthreads();
        if (tid < 256) {
            float s=0.f, q=0.f;
            #pragma unroll
            for (int w = 0; w < 16; w++){ s += xs[w*256 + tid]; q += xq[w*256 + tid]; }
            pSum[(size_t)blockIdx.x*FF + tid] = s;
            pSq [(size_t)blockIdx.x*FF + tid] = q;
        }
    }
}

// ============ node HMMA GEMM: 32 rows x 128 cols, K-stage 64 (4 stages), fp16 2-pass ============
#define N_PITCH 144
#define N_AHI 0
#define N_ALO 4608
#define N_B   9216
#define N_SMEM 27648
template<int AMODE, bool DOELU, bool STATS>
__global__ __launch_bounds__(256) void ngemm(
    const float* __restrict__ A,
    const __half* __restrict__ W,
    const float* __restrict__ bias,
    const float* __restrict__ aSc, const float* __restrict__ aSh,
    int ldc,
    float* __restrict__ C, float* __restrict__ pSum, float* __restrict__ pSq)
{
    __shared__ __align__(1024) char smem[N_SMEM];
    const uint32_t sb = smem_u32(smem);
    const int tid = threadIdx.x, wid = tid >> 5, l = tid & 31;
    const int rowbase = blockIdx.x * 32;
    const int cb = blockIdx.y * 128;

    const int m0  = (wid & 1) * 16;
    const int n0w = (wid >> 1) * 32;

    float acc[4][4];
    #pragma unroll
    for (int j=0;j<4;j++)
        #pragma unroll
        for (int q=0;q<4;q++) acc[j][q]=0.f;

    const uint32_t aHiBase = sb + N_AHI + (uint32_t)((m0 + (l & 15)) * N_PITCH + ((l >> 4) << 4));
    const int bro = (l & 7) + ((l >> 4) << 3);
    const uint32_t bBase = sb + N_B + (uint32_t)((n0w + bro) * N_PITCH + ((l & 8) ? 16 : 0));

    const int prow = tid >> 3, pko = (tid & 7) * 8;   // A: 32r x 64k, 8 el/thread
    const int bnr  = tid >> 1, bko = (tid & 1) * 32;  // B: 128n x 64k, 32 fp16/thread

    float4 fa0, fa1;
    uint4 bv[4];
    auto loadStage = [&](int ks){
        const int k0 = ks * 64;
        const float* pa = A + (size_t)(rowbase+prow)*FF + k0 + pko;
        fa0 = *(const float4*)pa; fa1 = *(const float4*)(pa+4);
        if (AMODE == 1) {
            const float4 sc0 = *(const float4*)(aSc + k0 + pko);
            const float4 sc1 = *(const float4*)(aSc + k0 + pko + 4);
            const float4 sh0 = *(const float4*)(aSh + k0 + pko);
            const float4 sh1 = *(const float4*)(aSh + k0 + pko + 4);
            fa0.x = fmaf(sc0.x, fa0.x, sh0.x); fa0.y = fmaf(sc0.y, fa0.y, sh0.y);
            fa0.z = fmaf(sc0.z, fa0.z, sh0.z); fa0.w = fmaf(sc0.w, fa0.w, sh0.w);
            fa1.x = fmaf(sc1.x, fa1.x, sh1.x); fa1.y = fmaf(sc1.y, fa1.y, sh1.y);
            fa1.z = fmaf(sc1.z, fa1.z, sh1.z); fa1.w = fmaf(sc1.w, fa1.w, sh1.w);
        }
        const size_t go = (size_t)(cb + bnr)*FF + k0 + bko;
        bv[0] = *(const uint4*)(W + go);      bv[1] = *(const uint4*)(W + go + 8);
        bv[2] = *(const uint4*)(W + go + 16); bv[3] = *(const uint4*)(W + go + 24);
    };

    loadStage(0);
    for (int ks = 0; ks < 4; ks++) {
        {
            uint32_t hi[4], lo[4];
            split2h(fa0.x, fa0.y, hi[0], lo[0]);
            split2h(fa0.z, fa0.w, hi[1], lo[1]);
            split2h(fa1.x, fa1.y, hi[2], lo[2]);
            split2h(fa1.z, fa1.w, hi[3], lo[3]);
            char* ah = smem + N_AHI + prow*N_PITCH + pko*2;
            char* al = smem + N_ALO + prow*N_PITCH + pko*2;
            *(uint4*)ah = make_uint4(hi[0],hi[1],hi[2],hi[3]);
            *(uint4*)al = make_uint4(lo[0],lo[1],lo[2],lo[3]);
        }
        {
            char* bh = smem + N_B + bnr*N_PITCH + bko*2;
            *(uint4*)bh      = bv[0]; *(uint4*)(bh+16) = bv[1];
            *(uint4*)(bh+32) = bv[2]; *(uint4*)(bh+48) = bv[3];
        }
        __syncthreads();
        if (ks < 3) loadStage(ks + 1);

        #pragma unroll
        for (int ksub = 0; ksub < 4; ksub++) {
            uint32_t ah[4], alr[4];
            uint32_t ad = aHiBase + (uint32_t)(ksub*32);
            LDSM4(ah[0],ah[1],ah[2],ah[3], ad);
            LDSM4(alr[0],alr[1],alr[2],alr[3], ad + (N_ALO-N_AHI));
            uint32_t bc[4], bn_[4];
            {
                uint32_t bd = bBase + (uint32_t)(ksub*32);
                LDSM4(bc[0],bc[1],bc[2],bc[3], bd);
            }
            #pragma unroll
            for (int nt2 = 0; nt2 < 2; nt2++) {
                if (nt2 < 1) {
                    uint32_t bd = bBase + (uint32_t)(16*N_PITCH + ksub*32);
                    LDSM4(bn_[0],bn_[1],bn_[2],bn_[3], bd);
                }
                #pragma unroll
                for (int t = 0; t < 2; t++) {
                    float* d = acc[nt2*2+t];
                    MMA4(d, ah[0],ah[1],ah[2],ah[3],   bc[t*2], bc[t*2+1]);
                    MMA4(d, alr[0],alr[1],alr[2],alr[3], bc[t*2], bc[t*2+1]);
                }
                #pragma unroll
                for (int q = 0; q < 4; q++) bc[q] = bn_[q];
            }
        }
        __syncthreads();
    }

    float* stage = (float*)smem;
    #pragma unroll
    for (int nt = 0; nt < 4; nt++) {
        int r = m0 + (l >> 2);
        int c = n0w + nt*8 + (l & 3)*2;
        stage[r*129 + c]       = acc[nt][0];
        stage[r*129 + c + 1]   = acc[nt][1];
        stage[(r+8)*129 + c]   = acc[nt][2];
        stage[(r+8)*129 + c+1] = acc[nt][3];
    }
    __syncthreads();

    float sS[4], sQ2[4];
    #pragma unroll
    for (int g = 0; g < 4; g++){ sS[g]=0.f; sQ2[g]=0.f; }
    #pragma unroll
    for (int rr = 0; rr < 4; rr++) {
        int r = wid*4 + rr;
        float* cp = C + (size_t)(rowbase + r)*ldc + cb;
        #pragma unroll
        for (int g = 0; g < 4; g++) {
            int c = g*32 + l;
            float f = stage[r*129 + c];
            if (bias) f += bias[cb + c];
            if (DOELU) f = eluf(f);
            cp[c] = f;
            if (STATS) { sS[g] += f; sQ2[g] = fmaf(f, f, sQ2[g]); }
        }
    }
    if (STATS) {
        __syncthreads();
        float* xs = (float*)(smem + 16512);
        float* xq = (float*)(smem + 20608);
        #pragma unroll
        for (int g = 0; g < 4; g++) {
            xs[wid*128 + g*32 + l] = sS[g];
            xq[wid*128 + g*32 + l] = sQ2[g];
        }
        __syncthreads();
        if (tid < 128) {
            float s=0.f, q=0.f;
            #pragma unroll
            for (int w = 0; w < 8; w++){ s += xs[w*128 + tid]; q += xq[w*128 + tid]; }
            pSum[(size_t)blockIdx.x*FF + cb + tid] = s;
            pSq [(size_t)blockIdx.x*FF + cb + tid] = q;
        }
    }
}

// ---------------- small kernels ----------------
__global__ void finalize_bn(const float* __restrict__ pSum, const float* __restrict__ pSq,
                            int nchunks, const float* __restrict__ g, const float* __restrict__ beta,
                            float invM, float* __restrict__ sc, float* __restrict__ sh)
{
    __shared__ float rs[256], rq[256];
    int lane = threadIdx.x & 31, part = threadIdx.x >> 5;
    int f = blockIdx.x*32 + lane;
    float s=0.f, q=0.f;
    for (int c=part; c<nchunks; c+=8){ s += pSum[(size_t)c*FF+f]; q += pSq[(size_t)c*FF+f]; }
    rs[threadIdx.x]=s; rq[threadIdx.x]=q;
    __syncthreads();
    if (part == 0){
        #pragma unroll
        for (int w=1; w<8; w++){ s += rs[w*32+lane]; q += rq[w*32+lane]; }
        float mean = s*invM;
        float var  = fmaf(-mean, mean, q*invM);
        float a = g[f]*rsqrtf(var + 1e-5f);
        sc[f]=a; sh[f] = fmaf(-mean, a, beta[f]);
    }
}

__global__ void edge2node_k(const float* __restrict__ h2, const float* __restrict__ sc,
                            const float* __restrict__ sh, float* __restrict__ inc)
{
    int bn = blockIdx.x; int b = bn >> 6; int n = bn & 63; int f = threadIdx.x;
    const float* base = h2 + (size_t)b*EE*FF + f;
    float s = 0.f;
    #pragma unroll
    for (int j=0;j<NN;j++){
        if (j==n) continue;
        int e = j*63 + (j < n ? n-1 : n);
        s += base[(size_t)e*FF];
    }
    inc[(size_t)bn*FF+f] = (sc[f]*s + 63.f*sh[f]) * (1.f/64.f);
}

struct TJob { const float* src; int srcOff; __half* dst; int dstOff; };
struct TJobs10 { TJob j[10]; };
__global__ void thalf_all(TJobs10 P)
{
    __shared__ float t[32][33];
    TJob jb = P.j[blockIdx.z];
    int k0 = blockIdx.x*32, n0 = blockIdx.y*32;
    int tx = threadIdx.x, ty = threadIdx.y;
    t[ty][tx] = jb.src[(size_t)(jb.srcOff + k0+ty)*FF + n0+tx];
    __syncthreads();
    jb.dst[(size_t)(jb.dstOff + n0+ty)*FF + k0+tx] = __float2half(t[tx][ty]);
}

__global__ void thalf_k(const float* __restrict__ src, const float* __restrict__ kscale,
                        __half* __restrict__ dst)
{
    __shared__ float t[32][33];
    int k0 = blockIdx.x*32, n0 = blockIdx.y*32;
    int tx = threadIdx.x, ty = threadIdx.y;
    t[ty][tx] = src[(size_t)(k0+ty)*FF + n0+tx] * kscale[k0+ty];
    __syncthreads();
    dst[(size_t)(n0+ty)*FF + k0+tx] = __float2half(t[tx][ty]);
}

__global__ void fill_biasPQ(const float* __restrict__ b1, float* __restrict__ biasPQ)
{
    int t = threadIdx.x;
    biasPQ[t] = b1[t];
    biasPQ[256+t] = 0.f;
}

__global__ void fold_dbias_k(const float* __restrict__ w1, const float* __restrict__ b1,
                             const float* __restrict__ sh2, float* __restrict__ db)
{
    int c = threadIdx.x;
    float s = b1[c];
    for (int f=0; f<FF; f++) s = fmaf(sh2[f], w1[(size_t)(512+f)*FF + c], s);
    db[c]=s;
}

__global__ void fold_fc_k(const float* __restrict__ fcw, const float* __restrict__ fcb,
                          const float* __restrict__ sc, const float* __restrict__ sh,
                          float* __restrict__ fcw2, float* __restrict__ fcb2)
{
    int t = threadIdx.x;
    fcw2[2*t]   = sc[t]*fcw[2*t];
    fcw2[2*t+1] = sc[t]*fcw[2*t+1];
    if (t < 2){
        float s = fcb[t];
        for (int f=0; f<FF; f++) s = fmaf(sh[f], fcw[2*f+t], s);
        fcb2[t]=s;
    }
}

__global__ void final_out_k(const float* __restrict__ h4, const float* __restrict__ fcw2,
                            const float* __restrict__ fcb2, float* __restrict__ out)
{
    int warpId = threadIdx.x >> 5; int lane = threadIdx.x & 31;
    int row = blockIdx.x*8 + warpId;
    const float* hr = h4 + (size_t)row*FF;
    float s0=0.f, s1=0.f;
    #pragma unroll
    for (int f=lane; f<FF; f+=32){
        float h = hr[f];
        s0 = fmaf(h, fcw2[2*f],   s0);
        s1 = fmaf(h, fcw2[2*f+1], s1);
    }
    #pragma unroll
    for (int o=16;o;o>>=1){
        s0 += __shfl_down_sync(0xffffffffu, s0, o);
        s1 += __shfl_down_sync(0xffffffffu, s1, o);
    }
    if (lane==0){ out[(size_t)row*2]=s0+fcb2[0]; out[(size_t)row*2+1]=s1+fcb2[1]; }
}

// ---------------- host ----------------
extern "C" void kernel_launch(void* const* d_in, const int* in_sizes, int n_in,
                              void* d_out, int out_size)
{
    (void)in_sizes; (void)n_in; (void)out_size;
    const float* inputs = (const float*)d_in[0];
    const float* m1w1=(const float*)d_in[3],  *m1b1=(const float*)d_in[4],
               * m1w2=(const float*)d_in[5],  *m1b2=(const float*)d_in[6],
               * m1g =(const float*)d_in[7],  *m1be=(const float*)d_in[8];
    const float* m2w1=(const float*)d_in[9],  *m2b1=(const float*)d_in[10],
               * m2w2=(const float*)d_in[11], *m2b2=(const float*)d_in[12],
               * m2g =(const float*)d_in[13], *m2be=(const float*)d_in[14];
    const float* m3w1=(const float*)d_in[15], *m3b1=(const float*)d_in[16],
               * m3w2=(const float*)d_in[17], *m3b2=(const float*)d_in[18],
               * m3g =(const float*)d_in[19], *m3be=(const float*)d_in[20];
    const float* m4w1=(const float*)d_in[21], *m4b1=(const float*)d_in[22],
               * m4w2=(const float*)d_in[23], *m4b2=(const float*)d_in[24],
               * m4g =(const float*)d_in[25], *m4be=(const float*)d_in[26];
    const float* fcw =(const float*)d_in[27], *fcb =(const float*)d_in[28];
    float* out = (float*)d_out;

    float *nodeA,*nodeB,*nodeC,*nodeD,*PQ,*SR,*inc,*bigA,*bigB;
    float *psum,*psq,*scale,*shift,*db,*biasPQ,*fcw2,*fcb2;
    __half *WL1,*WL2,*WL3,*WL4,*WPQ,*WSR,*W2,*W4,*WSK;
    cudaGetSymbolAddress((void**)&nodeA, g_nodeA);
    cudaGetSymbolAddress((void**)&nodeB, g_nodeB);
    cudaGetSymbolAddress((void**)&nodeC, g_nodeC);
    cudaGetSymbolAddress((void**)&nodeD, g_nodeD);
    cudaGetSymbolAddress((void**)&PQ,    g_PQ);
    cudaGetSymbolAddress((void**)&SR,    g_SR);
    cudaGetSymbolAddress((void**)&inc,   g_inc);
    cudaGetSymbolAddress((void**)&bigA,  g_bigA);
    cudaGetSymbolAddress((void**)&bigB,  g_bigB);
    cudaGetSymbolAddress((void**)&psum,  g_psum);
    cudaGetSymbolAddress((void**)&psq,   g_psq);
    cudaGetSymbolAddress((void**)&scale, g_scale);
    cudaGetSymbolAddress((void**)&shift, g_shift);
    cudaGetSymbolAddress((void**)&db,    g_dbias);
    cudaGetSymbolAddress((void**)&biasPQ,g_biasPQ);
    cudaGetSymbolAddress((void**)&fcw2,  g_fcw2);
    cudaGetSymbolAddress((void**)&fcb2,  g_fcb2);
    cudaGetSymbolAddress((void**)&WL1,   g_WL1);
    cudaGetSymbolAddress((void**)&WL2,   g_WL2);
    cudaGetSymbolAddress((void**)&WL3,   g_WL3);
    cudaGetSymbolAddress((void**)&WL4,   g_WL4);
    cudaGetSymbolAddress((void**)&WPQ,   g_WPQ);
    cudaGetSymbolAddress((void**)&WSR,   g_WSR);
    cudaGetSymbolAddress((void**)&W2,    g_W2);
    cudaGetSymbolAddress((void**)&W4,    g_W4);
    cudaGetSymbolAddress((void**)&WSK,   g_WSK);

    cudaFuncSetAttribute(hgemm<2,true,true ,false>, cudaFuncAttributeMaxDynamicSharedMemorySize, SMEM_DYN);
    cudaFuncSetAttribute(hgemm<0,true,false,true >, cudaFuncAttributeMaxDynamicSharedMemorySize, SMEM_DYN);
    cudaFuncSetAttribute(hgemm<0,true,true ,false>, cudaFuncAttributeMaxDynamicSharedMemorySize, SMEM_DYN);

    TJobs10 J;
    J.j[0] = { m1w1, 0,   WL1, 0   };
    J.j[1] = { m1w2, 0,   WL2, 0   };
    J.j[2] = { m2w1, 0,   WPQ, 0   };
    J.j[3] = { m2w1, 256, WPQ, 256 };
    J.j[4] = { m3w1, 0,   WL3, 0   };
    J.j[5] = { m3w2, 0,   WL4, 0   };
    J.j[6] = { m4w1, 0,   WSR, 0   };
    J.j[7] = { m4w1, 256, WSR, 256 };
    J.j[8] = { m2w2, 0,   W2,  0   };
    J.j[9] = { m4w2, 0,   W4,  0   };
    thalf_all<<<dim3(8,8,10), dim3(32,32)>>>(J);
    fill_biasPQ<<<1,256>>>(m2b1, biasPQ);

    dim3 gNode(NODE_CH, 2), gPQ(NODE_CH, 4), gBig(BIG_CH, 1);

    // mlp1 (node HMMA)
    ngemm<0,true,false><<<gNode,256>>>(inputs, WL1, m1b1, 0,0, FF, nodeA, 0,0);
    ngemm<0,true,true ><<<gNode,256>>>(nodeA , WL2, m1b2, 0,0, FF, nodeB, psum,psq);
    finalize_bn<<<8,256>>>(psum,psq,NODE_CH,m1g,m1be,1.f/NODE_M, scale,shift);

    // PQ = BN1(nodeB) @ [W_P | W_Q]
    ngemm<1,false,false><<<gPQ,256>>>(nodeB, WPQ, biasPQ, scale,shift, 512, PQ, 0,0);

    // big #1: bigA = elu( elu(P[s]+Q[r]) @ W2 + b2 ), stats -> BN2
    hgemm<2,true,true,false><<<gBig,512,SMEM_DYN>>>(PQ, PQ+256, W2, m2b2, 0,0,0, bigA, psum,psq);
    finalize_bn<<<8,256>>>(psum,psq,BIG_CH,m2g,m2be,1.f/BIG_M, scale+256,shift+256);

    thalf_k<<<dim3(8,8),dim3(32,32)>>>(m4w1 + 512*FF, scale+256, WSK);
    fold_dbias_k<<<1,256>>>(m4w1, m4b1, shift+256, db);

    edge2node_k<<<2048,256>>>(bigA, scale+256, shift+256, inc);

    // mlp3 (node HMMA)
    ngemm<0,true,false><<<gNode,256>>>(inc  , WL3, m3b1, 0,0, FF, nodeC, 0,0);
    ngemm<0,true,true ><<<gNode,256>>>(nodeC, WL4, m3b2, 0,0, FF, nodeD, psum,psq);
    finalize_bn<<<8,256>>>(psum,psq,NODE_CH,m3g,m3be,1.f/NODE_M, scale+512,shift+512);

    // SR = BN3(nodeD) @ [W_S | W_R]
    ngemm<1,false,false><<<gPQ,256>>>(nodeD, WSR, nullptr, scale+512,shift+512, 512, SR, 0,0);

    // big #2: bigB = elu( bigA @ Wskip + S[s] + R[r] + db )
    hgemm<0,true,false,true><<<gBig,512,SMEM_DYN>>>(bigA,0, WSK, nullptr, SR, SR+256, db, bigB, 0,0);
    // big #3: bigA = elu( bigB @ W4 + b2 ), stats -> BN4
    hgemm<0,true,true,false><<<gBig,512,SMEM_DYN>>>(bigB,0, W4, m4b2, 0,0,0, bigA, psum,psq);
    finalize_bn<<<8,256>>>(psum,psq,BIG_CH,m4g,m4be,1.f/BIG_M, scale+768,shift+768);

    fold_fc_k<<<1,256>>>(fcw, fcb, scale+768, shift+768, fcw2, fcb2);
    final_out_k<<<BIG_M/8,256>>>(bigA, fcw2, fcb2, out);
}